// round 10
// baseline (speedup 1.0000x reference)
#include <cuda_runtime.h>
#include <cuda_fp16.h>
#include <cuda_bf16.h>
#include <cstdint>
#include <cstdio>

#define DEV_INLINE __device__ __forceinline__

// ---------------------------------------------------------------------------
// Problem constants (fixed shapes)
// ---------------------------------------------------------------------------
constexpr int Bb   = 2;
constexpr int Ss   = 2048;
constexpr int HIDc = 2048;
constexpr int Hh   = 16;
constexpr int DNc  = 128;
constexpr int DRc  = 64;
constexpr int DVc  = 128;
constexpr int Rc   = 512;
constexpr int QHDc = DNc + DRc;             // 192
constexpr int MSc  = Bb * Ss;               // 4096 rows
constexpr int NKV  = Hh * QHDc + Hh * DVc;  // 5120 merged k|v cols
constexpr int NQD  = Hh * QHDc + Rc;        // 3584 merged q|ckv cols

// ---------------------------------------------------------------------------
// Scratch (static device globals; no allocation allowed)
// ---------------------------------------------------------------------------
__device__ __half g_hidden[MSc * HIDc];
__device__ __half g_Wqd [NQD * HIDc];         // rows 0..3071 = Wq, 3072..3583 = Wkv_down
__device__ __half g_Wkvuv[NKV * Rc];          // rows 0..3071 = Wkv_up, 3072..5119 = Wkv_v
__device__ __half g_Wo  [HIDc * Hh * DVc];
__device__ __half g_q   [Bb * Hh * Ss * QHDc];
__device__ __half g_k   [Bb * Hh * Ss * QHDc];
__device__ __half g_v   [Bb * Hh * Ss * DVc];
__device__ __half g_ckv_pre[MSc * Rc];        // pre-norm ckv (f16)
__device__ __half g_ckv [MSc * Rc];
__device__ __half g_attn[MSc * Hh * DVc];

// ---------------------------------------------------------------------------
// PTX helpers
// ---------------------------------------------------------------------------
DEV_INLINE uint32_t saddr(const void* p) {
    return (uint32_t)__cvta_generic_to_shared(p);
}
DEV_INLINE void ldm_x4(uint32_t& r0, uint32_t& r1, uint32_t& r2, uint32_t& r3, uint32_t a) {
    asm volatile("ldmatrix.sync.aligned.m8n8.x4.shared.b16 {%0,%1,%2,%3}, [%4];\n"
                 : "=r"(r0), "=r"(r1), "=r"(r2), "=r"(r3) : "r"(a));
}
DEV_INLINE void ldm_x4t(uint32_t& r0, uint32_t& r1, uint32_t& r2, uint32_t& r3, uint32_t a) {
    asm volatile("ldmatrix.sync.aligned.m8n8.x4.trans.shared.b16 {%0,%1,%2,%3}, [%4];\n"
                 : "=r"(r0), "=r"(r1), "=r"(r2), "=r"(r3) : "r"(a));
}
DEV_INLINE void mma_f16(float c[4], const uint32_t a[4], const uint32_t b0, const uint32_t b1) {
    asm volatile(
        "mma.sync.aligned.m16n8k16.row.col.f32.f16.f16.f32 "
        "{%0,%1,%2,%3},{%4,%5,%6,%7},{%8,%9},{%0,%1,%2,%3};\n"
        : "+f"(c[0]), "+f"(c[1]), "+f"(c[2]), "+f"(c[3])
        : "r"(a[0]), "r"(a[1]), "r"(a[2]), "r"(a[3]), "r"(b0), "r"(b1));
}
DEV_INLINE uint32_t packh(float a, float b) {
    __half2 h = __floats2half2_rn(a, b);
    return *reinterpret_cast<uint32_t*>(&h);
}

// cp.async helpers
DEV_INLINE void cp16(uint32_t dst_smem, const void* src) {
    asm volatile("cp.async.cg.shared.global [%0], [%1], 16;\n"
                 :: "r"(dst_smem), "l"(src));
}
DEV_INLINE void cp_commit() {
    asm volatile("cp.async.commit_group;\n" ::: "memory");
}
template <int N>
DEV_INLINE void cp_wait() {
    asm volatile("cp.async.wait_group %0;\n" :: "n"(N) : "memory");
}

// ---------------------------------------------------------------------------
// Fused f32 -> f16 convert for all 6 tensors (one launch).
// Wq/Wkv_down merge into g_Wqd; Wkv_up/Wkv_v merge into g_Wkvuv.
// ---------------------------------------------------------------------------
constexpr int N4_HID  = MSc * HIDc / 4;
constexpr int N4_WQ   = Hh * QHDc * HIDc / 4;
constexpr int N4_WKVD = Rc * HIDc / 4;
constexpr int N4_WKVU = Hh * QHDc * Rc / 4;
constexpr int N4_WKVV = Hh * DVc * Rc / 4;
constexpr int N4_WO   = HIDc * Hh * DVc / 4;
constexpr int N4_C0 = N4_HID;
constexpr int N4_C1 = N4_C0 + N4_WQ;
constexpr int N4_C2 = N4_C1 + N4_WKVD;
constexpr int N4_C3 = N4_C2 + N4_WKVU;
constexpr int N4_C4 = N4_C3 + N4_WKVV;
constexpr int N4_TOT = N4_C4 + N4_WO;

__global__ __launch_bounds__(256) void cvt_all_kernel(
    const float* __restrict__ hid, const float* __restrict__ wq,
    const float* __restrict__ wkvd, const float* __restrict__ wkvu,
    const float* __restrict__ wkvv, const float* __restrict__ wo,
    __half* __restrict__ d_hid, __half* __restrict__ d_wqd,
    __half* __restrict__ d_wkvuv, __half* __restrict__ d_wo) {
    int i = blockIdx.x * blockDim.x + threadIdx.x;
    if (i >= N4_TOT) return;
    const float* src;
    __half* dst;
    int j;
    if (i < N4_C0)      { src = hid;  dst = d_hid;  j = i; }
    else if (i < N4_C1) { src = wq;   dst = d_wqd;  j = i - N4_C0; }
    else if (i < N4_C2) { src = wkvd; dst = d_wqd + Hh * QHDc * HIDc; j = i - N4_C1; }
    else if (i < N4_C3) { src = wkvu; dst = d_wkvuv; j = i - N4_C2; }
    else if (i < N4_C4) { src = wkvv; dst = d_wkvuv + Hh * QHDc * Rc; j = i - N4_C3; }
    else                { src = wo;   dst = d_wo;   j = i - N4_C4; }
    float4 v = reinterpret_cast<const float4*>(src)[j];
    __half2 a = __floats2half2_rn(v.x, v.y);
    __half2 b = __floats2half2_rn(v.z, v.w);
    reinterpret_cast<__half2*>(dst)[2 * j + 0] = a;
    reinterpret_cast<__half2*>(dst)[2 * j + 1] = b;
}

// ---------------------------------------------------------------------------
// RMSNorm over R=512, f16 in -> f16 out (square-sum in f32)
// ---------------------------------------------------------------------------
__global__ __launch_bounds__(128) void rmsnorm_kernel(const __half* __restrict__ raw,
                                                      const float* __restrict__ w,
                                                      __half* __restrict__ out) {
    int row = blockIdx.x;
    const uint2* r2 = reinterpret_cast<const uint2*>(raw + (size_t)row * Rc);
    uint2 u = r2[threadIdx.x];
    __half2 h01 = *reinterpret_cast<__half2*>(&u.x);
    __half2 h23 = *reinterpret_cast<__half2*>(&u.y);
    float x0 = __low2float(h01), x1 = __high2float(h01);
    float x2 = __low2float(h23), x3 = __high2float(h23);
    float ss = x0 * x0 + x1 * x1 + x2 * x2 + x3 * x3;
    #pragma unroll
    for (int o = 16; o; o >>= 1) ss += __shfl_xor_sync(0xffffffffu, ss, o);
    __shared__ float red[4];
    if ((threadIdx.x & 31) == 0) red[threadIdx.x >> 5] = ss;
    __syncthreads();
    float tot = red[0] + red[1] + red[2] + red[3];
    float inv = rsqrtf(tot * (1.0f / (float)Rc) + 1e-5f);
    float4 wv = reinterpret_cast<const float4*>(w)[threadIdx.x];
    __half2 o0 = __floats2half2_rn(x0 * inv * wv.x, x1 * inv * wv.y);
    __half2 o1 = __floats2half2_rn(x2 * inv * wv.z, x3 * inv * wv.w);
    __half2* op = reinterpret_cast<__half2*>(out + (size_t)row * Rc + threadIdx.x * 4);
    op[0] = o0;
    op[1] = o1;
}

// ---------------------------------------------------------------------------
// RoPE in-place on q AND k (both [B,H,S,QHD] f16), rope dims [128,192)
// ---------------------------------------------------------------------------
__global__ __launch_bounds__(256) void rope_kernel(__half* __restrict__ Xq,
                                                   __half* __restrict__ Xk,
                                                   const float* __restrict__ cosT,
                                                   const float* __restrict__ sinT) {
    int idx = blockIdx.x * blockDim.x + threadIdx.x;
    int j = idx & 31;
    int row = idx >> 5;
    const int nrows = Bb * Hh * Ss;
    if (row >= 2 * nrows) return;
    __half* X = (row < nrows) ? Xq : Xk;
    if (row >= nrows) row -= nrows;
    int s = row & (Ss - 1);
    __half* base = X + (size_t)row * QHDc + DNc;
    float x1 = __half2float(base[j]);
    float x2 = __half2float(base[j + 32]);
    float c1 = cosT[s * DRc + j];
    float s1 = sinT[s * DRc + j];
    float c2 = cosT[s * DRc + 32 + j];
    float s2 = sinT[s * DRc + 32 + j];
    base[j]      = __float2half_rn(x1 * c1 - x2 * s1);
    base[j + 32] = __float2half_rn(x2 * c2 + x1 * s2);
}

// ---------------------------------------------------------------------------
// NT GEMM, cp.async 3-stage pipeline, BK=64, coalesced smem-staged epilogue.
// EPI: 0 = f32 plain
//      3 = merged k|v scatter: col<3072 -> g_k, else -> g_v
//      4 = merged q|ckv scatter: col<3072 -> g_q, else -> g_ckv_pre (f16 linear)
// ---------------------------------------------------------------------------
constexpr int GBK      = 64;
constexpr int SMST     = 72;
constexpr int GSTAGES  = 3;
constexpr int STAGE_HALVES = 128 * SMST;
constexpr int GEMM_SMEM = GSTAGES * 2 * STAGE_HALVES * (int)sizeof(__half);  // 110592
constexpr int EPI_F32_STRIDE = 132;
constexpr int EPI_F16_STRIDE = 136;
static_assert(128 * EPI_F32_STRIDE * 4 <= GEMM_SMEM, "f32 stage fits");

template <int EPI>
__global__ __launch_bounds__(256, 2) void gemm_nt(const __half* __restrict__ A,
                                                  const __half* __restrict__ Bw,
                                                  float* __restrict__ outF,
                                                  __half* __restrict__ outH,
                                                  int M, int N, int K) {
    extern __shared__ __half gsm[];

    const int tid = threadIdx.x;
    const int lane = tid & 31, warp = tid >> 5;
    const int wm = (warp & 3) * 32, wn = (warp >> 2) * 64;
    const int m0 = blockIdx.y * 128, n0 = blockIdx.x * 128;

    const __half* Ag = A + (size_t)m0 * K;
    const __half* Bg = Bw + (size_t)n0 * K;

    auto stageA = [&](int s) -> __half* { return gsm + s * 2 * STAGE_HALVES; };
    auto stageB = [&](int s) -> __half* { return gsm + s * 2 * STAGE_HALVES + STAGE_HALVES; };

    auto issue = [&](int s, int kc) {
        __half* sa = stageA(s);
        __half* sb = stageB(s);
        const __half* ag = Ag + (size_t)kc * GBK;
        const __half* bg = Bg + (size_t)kc * GBK;
        #pragma unroll
        for (int p = 0; p < 4; p++) {
            int idx = tid + p * 256;
            int r = idx >> 3;
            int c = (idx & 7) * 8;
            cp16(saddr(sa + r * SMST + c), ag + (size_t)r * K + c);
            cp16(saddr(sb + r * SMST + c), bg + (size_t)r * K + c);
        }
    };

    float acc[2][8][4];
    #pragma unroll
    for (int i = 0; i < 2; i++)
        #pragma unroll
        for (int j = 0; j < 8; j++)
            #pragma unroll
            for (int r = 0; r < 4; r++) acc[i][j][r] = 0.f;

    const int nk = K / GBK;

    issue(0, 0); cp_commit();
    issue(1, 1); cp_commit();

    for (int kc = 0; kc < nk; kc++) {
        cp_wait<1>();
        __syncthreads();
        const int s = kc % 3;
        const __half* sa = stageA(s);
        const __half* sb = stageB(s);

        #pragma unroll
        for (int ks = 0; ks < 4; ks++) {
            uint32_t af[2][4];
            #pragma unroll
            for (int mi = 0; mi < 2; mi++) {
                uint32_t a = saddr(&sa[(wm + mi * 16 + (lane & 15)) * SMST + ks * 16 + (lane >> 4) * 8]);
                ldm_x4(af[mi][0], af[mi][1], af[mi][2], af[mi][3], a);
            }
            uint32_t bf[8][2];
            #pragma unroll
            for (int j = 0; j < 4; j++) {
                uint32_t r0, r1, r2, r3;
                uint32_t a = saddr(&sb[(wn + j * 16 + (lane & 15)) * SMST + ks * 16 + (lane >> 4) * 8]);
                ldm_x4(r0, r1, r2, r3, a);
                bf[2 * j + 0][0] = r0; bf[2 * j + 0][1] = r2;
                bf[2 * j + 1][0] = r1; bf[2 * j + 1][1] = r3;
            }
            #pragma unroll
            for (int mi = 0; mi < 2; mi++)
                #pragma unroll
                for (int j = 0; j < 8; j++)
                    mma_f16(acc[mi][j], af[mi], bf[j][0], bf[j][1]);
        }

        if (kc + 2 < nk) issue((kc + 2) % 3, kc + 2);
        cp_commit();
    }

    // ---------------- epilogue: stage C in smem, write coalesced ------------
    cp_wait<0>();
    __syncthreads();

    const int g = lane >> 2, t = lane & 3;
    if (EPI == 0) {
        float* cs = reinterpret_cast<float*>(gsm);
        #pragma unroll
        for (int mi = 0; mi < 2; mi++)
            #pragma unroll
            for (int j = 0; j < 8; j++)
                #pragma unroll
                for (int hh = 0; hh < 2; hh++) {
                    int r = wm + mi * 16 + g + hh * 8;
                    int c = wn + j * 8 + t * 2;
                    cs[r * EPI_F32_STRIDE + c + 0] = acc[mi][j][hh * 2 + 0];
                    cs[r * EPI_F32_STRIDE + c + 1] = acc[mi][j][hh * 2 + 1];
                }
        __syncthreads();
        #pragma unroll
        for (int p = 0; p < 16; p++) {
            int chunk = tid + p * 256;
            int r = chunk >> 5, cc = (chunk & 31) * 4;
            float4 v = *reinterpret_cast<const float4*>(&cs[r * EPI_F32_STRIDE + cc]);
            *reinterpret_cast<float4*>(&outF[(size_t)(m0 + r) * N + n0 + cc]) = v;
        }
    } else {
        __half* cs = gsm;
        #pragma unroll
        for (int mi = 0; mi < 2; mi++)
            #pragma unroll
            for (int j = 0; j < 8; j++)
                #pragma unroll
                for (int hh = 0; hh < 2; hh++) {
                    int r = wm + mi * 16 + g + hh * 8;
                    int c = wn + j * 8 + t * 2;
                    *reinterpret_cast<__half2*>(&cs[r * EPI_F16_STRIDE + c]) =
                        __floats2half2_rn(acc[mi][j][hh * 2 + 0], acc[mi][j][hh * 2 + 1]);
                }
        __syncthreads();
        #pragma unroll
        for (int p = 0; p < 8; p++) {
            int chunk = tid + p * 256;
            int r = chunk >> 4, cc = (chunk & 15) * 8;
            uint4 v = *reinterpret_cast<const uint4*>(&cs[r * EPI_F16_STRIDE + cc]);
            int row = m0 + r;
            int col = n0 + cc;
            int b = row >> 11, s = row & (Ss - 1);
            if (EPI == 3) {  // merged k|v scatter
                if (col < Hh * QHDc) {
                    int h = col / QHDc, d = col - h * QHDc;
                    size_t di = (((size_t)b * Hh + h) * Ss + s) * QHDc + d;
                    *reinterpret_cast<uint4*>(&g_k[di]) = v;
                } else {
                    int c2 = col - Hh * QHDc;
                    int h = c2 >> 7, d = c2 & (DVc - 1);
                    size_t di = (((size_t)b * Hh + h) * Ss + s) * DVc + d;
                    *reinterpret_cast<uint4*>(&g_v[di]) = v;
                }
            } else {  // EPI == 4: merged q|ckv scatter
                if (col < Hh * QHDc) {
                    int h = col / QHDc, d = col - h * QHDc;
                    size_t di = (((size_t)b * Hh + h) * Ss + s) * QHDc + d;
                    *reinterpret_cast<uint4*>(&g_q[di]) = v;
                } else {
                    size_t di = (size_t)row * Rc + (col - Hh * QHDc);
                    *reinterpret_cast<uint4*>(&g_ckv_pre[di]) = v;
                }
            }
        }
    }
}

// ---------------------------------------------------------------------------
// Flash attention: per CTA one (b,h,qtile=64 rows). 4 warps, 3 CTAs/SM.
// Q fragments live in REGISTERS; Q's old smem slot becomes K's double buffer.
// K(kt+1) prefetched via cp.async during softmax/PV; V(kt) loads during QK.
// No-max exp2 softmax.
// ---------------------------------------------------------------------------
constexpr int QSTRIDE = 200;  // 192 + 8 pad
constexpr int VSTRIDE = 136;  // 128 + 8 pad
constexpr int ATTN_SMEM_BYTES = (2 * 64 * QSTRIDE + 64 * VSTRIDE) * (int)sizeof(__half); // 68608

__global__ __launch_bounds__(128, 3) void attn_kernel(const __half* __restrict__ Q,
                                                      const __half* __restrict__ Kt,
                                                      const __half* __restrict__ V,
                                                      __half* __restrict__ Out) {
    extern __shared__ __half sm[];
    __half* sKb[2] = {sm, sm + 64 * QSTRIDE};
    __half* sV = sm + 2 * 64 * QSTRIDE;

    const int qt = (int)gridDim.x - 1 - (int)blockIdx.x;  // heavy tiles first
    const int h = blockIdx.y, b = blockIdx.z;
    const int tid = threadIdx.x, lane = tid & 31, warp = tid >> 5;
    const int g = lane >> 2, t = lane & 3;
    const int wq = warp * 16;

    const size_t bh = (size_t)b * Hh + h;
    const __half* Qg = Q + (bh * Ss + (size_t)qt * 64) * QHDc;
    const __half* Kg = Kt + bh * Ss * QHDc;
    const __half* Vg = V + bh * Ss * DVc;

    auto issue_k = [&](int kt, int buf) {
        __half* sk = sKb[buf];
        #pragma unroll
        for (int p = 0; p < 12; p++) {
            int idx = tid + p * 128;
            int r = idx / 24, c = (idx % 24) * 8;
            cp16(saddr(&sk[r * QSTRIDE + c]), &Kg[((size_t)kt * 64 + r) * QHDc + c]);
        }
    };
    auto issue_v = [&](int kt) {
        #pragma unroll
        for (int p = 0; p < 8; p++) {
            int idx = tid + p * 128;
            int r = idx >> 4, c = (idx & 15) * 8;
            cp16(saddr(&sV[r * VSTRIDE + c]), &Vg[((size_t)kt * 64 + r) * DVc + c]);
        }
    };

    // prologue: Q -> smem (buffer 0) -> registers, then start K(0) prefetch
    #pragma unroll
    for (int p = 0; p < 12; p++) {
        int idx = tid + p * 128;
        int r = idx / 24, c = (idx % 24) * 8;
        *reinterpret_cast<uint4*>(&sKb[0][r * QSTRIDE + c]) =
            *reinterpret_cast<const uint4*>(&Qg[(size_t)r * QHDc + c]);
    }
    __syncthreads();
    uint32_t qf[12][4];
    #pragma unroll
    for (int ks = 0; ks < 12; ks++) {
        ldm_x4(qf[ks][0], qf[ks][1], qf[ks][2], qf[ks][3],
               saddr(&sKb[0][(wq + (lane & 15)) * QSTRIDE + ks * 16 + (lane >> 4) * 8]));
    }
    __syncthreads();  // all Q reads done before K(0) overwrites buffer 0
    issue_k(0, 0);
    cp_commit();

    float o[16][4];
    #pragma unroll
    for (int i = 0; i < 16; i++)
        #pragma unroll
        for (int r = 0; r < 4; r++) o[i][r] = 0.f;
    float lrow[2] = {0.f, 0.f};
    const float scale2 = 0.07216878364870323f * 1.4426950408889634f;  // /sqrt(192)*log2e

    const int nkt = qt + 1;
    for (int kt = 0; kt < nkt; kt++) {
        const int cur = kt & 1;
        __syncthreads();          // sV free of previous PV readers
        issue_v(kt);
        cp_commit();
        cp_wait<1>();             // K(kt) arrived (V(kt) may be in flight)
        __syncthreads();
        const __half* sK = sKb[cur];

        float sacc[8][4];
        #pragma unroll
        for (int j = 0; j < 8; j++)
            #pragma unroll
            for (int r = 0; r < 4; r++) sacc[j][r] = 0.f;

        #pragma unroll
        for (int ks = 0; ks < 12; ks++) {
            #pragma unroll
            for (int j = 0; j < 4; j++) {
                uint32_t r0, r1, r2, r3;
                ldm_x4(r0, r1, r2, r3,
                       saddr(&sK[(j * 16 + (lane & 15)) * QSTRIDE + ks * 16 + (lane >> 4) * 8]));
                mma_f16(sacc[2 * j + 0], qf[ks], r0, r2);
                mma_f16(sacc[2 * j + 1], qf[ks], r1, r3);
            }
        }

        // prefetch next K tile while softmax + PV run
        if (kt < qt) issue_k(kt + 1, cur ^ 1);
        cp_commit();

        const bool diag = (kt == qt);
        #pragma unroll
        for (int hh = 0; hh < 2; hh++) {
            float sum = 0.f;
            #pragma unroll
            for (int j = 0; j < 8; j++) {
                float s0 = sacc[j][hh * 2 + 0] * scale2;
                float s1 = sacc[j][hh * 2 + 1] * scale2;
                if (diag) {
                    int col = kt * 64 + j * 8 + t * 2;
                    int qrow = qt * 64 + wq + g + hh * 8;
                    if (col > qrow)     s0 = -1e30f;
                    if (col + 1 > qrow) s1 = -1e30f;
                }
                float p0 = exp2f(s0);
                float p1 = exp2f(s1);
                sacc[j][hh * 2 + 0] = p0;
                sacc[j][hh * 2 + 1] = p1;
                sum += p0 + p1;
            }
            sum += __shfl_xor_sync(0xffffffffu, sum, 1);
            sum += __shfl_xor_sync(0xffffffffu, sum, 2);
            lrow[hh] += sum;
        }

        uint32_t pa[4][4];
        #pragma unroll
        for (int kk = 0; kk < 4; kk++) {
            pa[kk][0] = packh(sacc[2 * kk][0], sacc[2 * kk][1]);
            pa[kk][1] = packh(sacc[2 * kk][2], sacc[2 * kk][3]);
            pa[kk][2] = packh(sacc[2 * kk + 1][0], sacc[2 * kk + 1][1]);
            pa[kk][3] = packh(sacc[2 * kk + 1][2], sacc[2 * kk + 1][3]);
        }

        cp_wait<1>();             // V(kt) arrived (K(kt+1) may be in flight)
        __syncthreads();

        #pragma unroll
        for (int kk = 0; kk < 4; kk++) {
            #pragma unroll
            for (int jg = 0; jg < 8; jg++) {
                uint32_t r0, r1, r2, r3;
                ldm_x4t(r0, r1, r2, r3,
                        saddr(&sV[(kk * 16 + (lane & 15)) * VSTRIDE + jg * 16 + (lane >> 4) * 8]));
                mma_f16(o[2 * jg + 0], pa[kk], r0, r1);
                mma_f16(o[2 * jg + 1], pa[kk], r2, r3);
            }
        }
    }

    float inv0 = 1.f / lrow[0];
    float inv1 = 1.f / lrow[1];
    #pragma unroll
    for (int nt = 0; nt < 16; nt++) {
        #pragma unroll
        for (int hh = 0; hh < 2; hh++) {
            float inv = hh ? inv1 : inv0;
            int srow = qt * 64 + wq + g + hh * 8;
            int col = nt * 8 + t * 2;
            __half2 hv = __floats2half2_rn(o[nt][hh * 2] * inv, o[nt][hh * 2 + 1] * inv);
            size_t di = ((size_t)b * Ss + srow) * (Hh * DVc) + (size_t)h * DVc + col;
            *reinterpret_cast<__half2*>(&Out[di]) = hv;
        }
    }
}

// ---------------------------------------------------------------------------
// Host launcher
// ---------------------------------------------------------------------------
static void* symaddr(const void* sym) {
    void* p = nullptr;
    cudaGetSymbolAddress(&p, sym);
    return p;
}

extern "C" void kernel_launch(void* const* d_in, const int* in_sizes, int n_in,
                              void* d_out, int out_size) {
    const float* hidden = (const float*)d_in[0];
    const float* Wq    = (const float*)d_in[3];
    const float* Wkvd  = (const float*)d_in[4];
    const float* normw = (const float*)d_in[5];
    const float* Wkvu  = (const float*)d_in[6];
    const float* Wkvv  = (const float*)d_in[7];
    const float* Wo    = (const float*)d_in[8];
    const float* cosT  = (const float*)d_in[9];
    const float* sinT  = (const float*)d_in[10];
    float* out = (float*)d_out;

    __half* p_hidden = (__half*)symaddr(g_hidden);
    __half* p_Wqd    = (__half*)symaddr(g_Wqd);
    __half* p_Wkvuv  = (__half*)symaddr(g_Wkvuv);
    __half* p_Wo     = (__half*)symaddr(g_Wo);
    __half* p_q      = (__half*)symaddr(g_q);
    __half* p_k      = (__half*)symaddr(g_k);
    __half* p_v      = (__half*)symaddr(g_v);
    __half* p_ckvpre = (__half*)symaddr(g_ckv_pre);
    __half* p_ckv    = (__half*)symaddr(g_ckv);
    __half* p_attn   = (__half*)symaddr(g_attn);

    // launch 0: fused convert
    cvt_all_kernel<<<(N4_TOT + 255) / 256, 256>>>(
        hidden, Wq, Wkvd, Wkvu, Wkvv, Wo,
        p_hidden, p_Wqd, p_Wkvuv, p_Wo);

    cudaFuncSetAttribute(gemm_nt<0>, cudaFuncAttributeMaxDynamicSharedMemorySize, GEMM_SMEM);
    cudaFuncSetAttribute(gemm_nt<3>, cudaFuncAttributeMaxDynamicSharedMemorySize, GEMM_SMEM);
    cudaFuncSetAttribute(gemm_nt<4>, cudaFuncAttributeMaxDynamicSharedMemorySize, GEMM_SMEM);

    // launch 1: merged q|ckv = hidden @ [Wq;Wkv_down]^T (scatter q + ckv_pre)
    gemm_nt<4><<<dim3(NQD / 128, MSc / 128), 256, GEMM_SMEM>>>(
        p_hidden, p_Wqd, nullptr, nullptr, MSc, NQD, HIDc);
    // launch 2: rmsnorm (f16 in -> f16 out)
    rmsnorm_kernel<<<MSc, 128>>>(p_ckvpre, normw, p_ckv);
    // launch 3: merged k|v = ckv @ [Wkv_up;Wkv_v]^T (PROFILED idx 3)
    gemm_nt<3><<<dim3(NKV / 128, MSc / 128), 256, GEMM_SMEM>>>(
        p_ckv, p_Wkvuv, nullptr, nullptr, MSc, NKV, Rc);
    // launch 4: RoPE on q and k (fused)
    {
        int total = 2 * Bb * Hh * Ss * 32;
        rope_kernel<<<(total + 255) / 256, 256>>>(p_q, p_k, cosT, sinT);
    }
    // launch 5: attention (64-row tiles, Q-in-regs, K double-buffered cp.async)
    cudaFuncSetAttribute(attn_kernel, cudaFuncAttributeMaxDynamicSharedMemorySize,
                         ATTN_SMEM_BYTES);
    attn_kernel<<<dim3(Ss / 64, Hh, Bb), 128, ATTN_SMEM_BYTES>>>(p_q, p_k, p_v, p_attn);
    // launch 6: out = attn @ Wo^T (f32, straight to d_out)
    gemm_nt<0><<<dim3(HIDc / 128, MSc / 128), 256, GEMM_SMEM>>>(
        p_attn, p_Wo, out, nullptr, MSc, HIDc, HIDc);
}

// round 12
// speedup vs baseline: 1.0374x; 1.0374x over previous
#include <cuda_runtime.h>
#include <cuda_fp16.h>
#include <cuda_bf16.h>
#include <cstdint>
#include <cstdio>

#define DEV_INLINE __device__ __forceinline__

// ---------------------------------------------------------------------------
// Problem constants (fixed shapes)
// ---------------------------------------------------------------------------
constexpr int Bb   = 2;
constexpr int Ss   = 2048;
constexpr int HIDc = 2048;
constexpr int Hh   = 16;
constexpr int DNc  = 128;
constexpr int DRc  = 64;
constexpr int DVc  = 128;
constexpr int Rc   = 512;
constexpr int QHDc = DNc + DRc;             // 192
constexpr int MSc  = Bb * Ss;               // 4096 rows
constexpr int NKV  = Hh * QHDc + Hh * DVc;  // 5120 merged k|v cols
constexpr int NQD  = Hh * QHDc + Rc;        // 3584 merged q|ckv cols

// ---------------------------------------------------------------------------
// Scratch (static device globals; no allocation allowed)
// ---------------------------------------------------------------------------
__device__ __half g_hidden[MSc * HIDc];
__device__ __half g_Wqd [NQD * HIDc];         // rows 0..3071 = Wq, 3072..3583 = Wkv_down
__device__ __half g_Wkvuv[NKV * Rc];          // rows 0..3071 = Wkv_up, 3072..5119 = Wkv_v
__device__ __half g_Wo  [HIDc * Hh * DVc];
__device__ __half g_q   [Bb * Hh * Ss * QHDc];
__device__ __half g_k   [Bb * Hh * Ss * QHDc];
__device__ __half g_v   [Bb * Hh * Ss * DVc];
__device__ __half g_ckv_pre[MSc * Rc];        // pre-norm ckv (f16)
__device__ __half g_ckv [MSc * Rc];
__device__ __half g_attn[MSc * Hh * DVc];

// ---------------------------------------------------------------------------
// PTX helpers
// ---------------------------------------------------------------------------
DEV_INLINE uint32_t saddr(const void* p) {
    return (uint32_t)__cvta_generic_to_shared(p);
}
DEV_INLINE void ldm_x4(uint32_t& r0, uint32_t& r1, uint32_t& r2, uint32_t& r3, uint32_t a) {
    asm volatile("ldmatrix.sync.aligned.m8n8.x4.shared.b16 {%0,%1,%2,%3}, [%4];\n"
                 : "=r"(r0), "=r"(r1), "=r"(r2), "=r"(r3) : "r"(a));
}
DEV_INLINE void ldm_x4t(uint32_t& r0, uint32_t& r1, uint32_t& r2, uint32_t& r3, uint32_t a) {
    asm volatile("ldmatrix.sync.aligned.m8n8.x4.trans.shared.b16 {%0,%1,%2,%3}, [%4];\n"
                 : "=r"(r0), "=r"(r1), "=r"(r2), "=r"(r3) : "r"(a));
}
DEV_INLINE void mma_f16(float c[4], const uint32_t a[4], const uint32_t b0, const uint32_t b1) {
    asm volatile(
        "mma.sync.aligned.m16n8k16.row.col.f32.f16.f16.f32 "
        "{%0,%1,%2,%3},{%4,%5,%6,%7},{%8,%9},{%0,%1,%2,%3};\n"
        : "+f"(c[0]), "+f"(c[1]), "+f"(c[2]), "+f"(c[3])
        : "r"(a[0]), "r"(a[1]), "r"(a[2]), "r"(a[3]), "r"(b0), "r"(b1));
}
DEV_INLINE uint32_t packh(float a, float b) {
    __half2 h = __floats2half2_rn(a, b);
    return *reinterpret_cast<uint32_t*>(&h);
}

// cp.async helpers
DEV_INLINE void cp16(uint32_t dst_smem, const void* src) {
    asm volatile("cp.async.cg.shared.global [%0], [%1], 16;\n"
                 :: "r"(dst_smem), "l"(src));
}
DEV_INLINE void cp_commit() {
    asm volatile("cp.async.commit_group;\n" ::: "memory");
}
template <int N>
DEV_INLINE void cp_wait() {
    asm volatile("cp.async.wait_group %0;\n" :: "n"(N) : "memory");
}

// ---------------------------------------------------------------------------
// Fused f32 -> f16 convert for all 6 tensors (one launch).
// Wq/Wkv_down merge into g_Wqd; Wkv_up/Wkv_v merge into g_Wkvuv.
// ---------------------------------------------------------------------------
constexpr int N4_HID  = MSc * HIDc / 4;
constexpr int N4_WQ   = Hh * QHDc * HIDc / 4;
constexpr int N4_WKVD = Rc * HIDc / 4;
constexpr int N4_WKVU = Hh * QHDc * Rc / 4;
constexpr int N4_WKVV = Hh * DVc * Rc / 4;
constexpr int N4_WO   = HIDc * Hh * DVc / 4;
constexpr int N4_C0 = N4_HID;
constexpr int N4_C1 = N4_C0 + N4_WQ;
constexpr int N4_C2 = N4_C1 + N4_WKVD;
constexpr int N4_C3 = N4_C2 + N4_WKVU;
constexpr int N4_C4 = N4_C3 + N4_WKVV;
constexpr int N4_TOT = N4_C4 + N4_WO;

__global__ __launch_bounds__(256) void cvt_all_kernel(
    const float* __restrict__ hid, const float* __restrict__ wq,
    const float* __restrict__ wkvd, const float* __restrict__ wkvu,
    const float* __restrict__ wkvv, const float* __restrict__ wo,
    __half* __restrict__ d_hid, __half* __restrict__ d_wqd,
    __half* __restrict__ d_wkvuv, __half* __restrict__ d_wo) {
    int i = blockIdx.x * blockDim.x + threadIdx.x;
    if (i >= N4_TOT) return;
    const float* src;
    __half* dst;
    int j;
    if (i < N4_C0)      { src = hid;  dst = d_hid;  j = i; }
    else if (i < N4_C1) { src = wq;   dst = d_wqd;  j = i - N4_C0; }
    else if (i < N4_C2) { src = wkvd; dst = d_wqd + Hh * QHDc * HIDc; j = i - N4_C1; }
    else if (i < N4_C3) { src = wkvu; dst = d_wkvuv; j = i - N4_C2; }
    else if (i < N4_C4) { src = wkvv; dst = d_wkvuv + Hh * QHDc * Rc; j = i - N4_C3; }
    else                { src = wo;   dst = d_wo;   j = i - N4_C4; }
    float4 v = reinterpret_cast<const float4*>(src)[j];
    __half2 a = __floats2half2_rn(v.x, v.y);
    __half2 b = __floats2half2_rn(v.z, v.w);
    reinterpret_cast<__half2*>(dst)[2 * j + 0] = a;
    reinterpret_cast<__half2*>(dst)[2 * j + 1] = b;
}

// ---------------------------------------------------------------------------
// RMSNorm over R=512, f16 in -> f16 out (square-sum in f32)
// ---------------------------------------------------------------------------
__global__ __launch_bounds__(128) void rmsnorm_kernel(const __half* __restrict__ raw,
                                                      const float* __restrict__ w,
                                                      __half* __restrict__ out) {
    int row = blockIdx.x;
    const uint2* r2 = reinterpret_cast<const uint2*>(raw + (size_t)row * Rc);
    uint2 u = r2[threadIdx.x];
    __half2 h01 = *reinterpret_cast<__half2*>(&u.x);
    __half2 h23 = *reinterpret_cast<__half2*>(&u.y);
    float x0 = __low2float(h01), x1 = __high2float(h01);
    float x2 = __low2float(h23), x3 = __high2float(h23);
    float ss = x0 * x0 + x1 * x1 + x2 * x2 + x3 * x3;
    #pragma unroll
    for (int o = 16; o; o >>= 1) ss += __shfl_xor_sync(0xffffffffu, ss, o);
    __shared__ float red[4];
    if ((threadIdx.x & 31) == 0) red[threadIdx.x >> 5] = ss;
    __syncthreads();
    float tot = red[0] + red[1] + red[2] + red[3];
    float inv = rsqrtf(tot * (1.0f / (float)Rc) + 1e-5f);
    float4 wv = reinterpret_cast<const float4*>(w)[threadIdx.x];
    __half2 o0 = __floats2half2_rn(x0 * inv * wv.x, x1 * inv * wv.y);
    __half2 o1 = __floats2half2_rn(x2 * inv * wv.z, x3 * inv * wv.w);
    __half2* op = reinterpret_cast<__half2*>(out + (size_t)row * Rc + threadIdx.x * 4);
    op[0] = o0;
    op[1] = o1;
}

// ---------------------------------------------------------------------------
// RoPE in-place on q AND k (both [B,H,S,QHD] f16), rope dims [128,192)
// ---------------------------------------------------------------------------
__global__ __launch_bounds__(256) void rope_kernel(__half* __restrict__ Xq,
                                                   __half* __restrict__ Xk,
                                                   const float* __restrict__ cosT,
                                                   const float* __restrict__ sinT) {
    int idx = blockIdx.x * blockDim.x + threadIdx.x;
    int j = idx & 31;
    int row = idx >> 5;
    const int nrows = Bb * Hh * Ss;
    if (row >= 2 * nrows) return;
    __half* X = (row < nrows) ? Xq : Xk;
    if (row >= nrows) row -= nrows;
    int s = row & (Ss - 1);
    __half* base = X + (size_t)row * QHDc + DNc;
    float x1 = __half2float(base[j]);
    float x2 = __half2float(base[j + 32]);
    float c1 = cosT[s * DRc + j];
    float s1 = sinT[s * DRc + j];
    float c2 = cosT[s * DRc + 32 + j];
    float s2 = sinT[s * DRc + 32 + j];
    base[j]      = __float2half_rn(x1 * c1 - x2 * s1);
    base[j + 32] = __float2half_rn(x2 * c2 + x1 * s2);
}

// ---------------------------------------------------------------------------
// NT GEMM, cp.async 3-stage pipeline, BK=64, coalesced smem-staged epilogue.
// EPI: 0 = f32 plain
//      3 = merged k|v scatter: col<3072 -> g_k, else -> g_v
//      4 = merged q|ckv scatter: col<3072 -> g_q, else -> g_ckv_pre (f16 linear)
// ---------------------------------------------------------------------------
constexpr int GBK      = 64;
constexpr int SMST     = 72;
constexpr int GSTAGES  = 3;
constexpr int STAGE_HALVES = 128 * SMST;
constexpr int GEMM_SMEM = GSTAGES * 2 * STAGE_HALVES * (int)sizeof(__half);  // 110592
constexpr int EPI_F32_STRIDE = 132;
constexpr int EPI_F16_STRIDE = 136;
static_assert(128 * EPI_F32_STRIDE * 4 <= GEMM_SMEM, "f32 stage fits");

template <int EPI>
__global__ __launch_bounds__(256, 2) void gemm_nt(const __half* __restrict__ A,
                                                  const __half* __restrict__ Bw,
                                                  float* __restrict__ outF,
                                                  __half* __restrict__ outH,
                                                  int M, int N, int K) {
    extern __shared__ __half gsm[];

    const int tid = threadIdx.x;
    const int lane = tid & 31, warp = tid >> 5;
    const int wm = (warp & 3) * 32, wn = (warp >> 2) * 64;
    const int m0 = blockIdx.y * 128, n0 = blockIdx.x * 128;

    const __half* Ag = A + (size_t)m0 * K;
    const __half* Bg = Bw + (size_t)n0 * K;

    auto stageA = [&](int s) -> __half* { return gsm + s * 2 * STAGE_HALVES; };
    auto stageB = [&](int s) -> __half* { return gsm + s * 2 * STAGE_HALVES + STAGE_HALVES; };

    auto issue = [&](int s, int kc) {
        __half* sa = stageA(s);
        __half* sb = stageB(s);
        const __half* ag = Ag + (size_t)kc * GBK;
        const __half* bg = Bg + (size_t)kc * GBK;
        #pragma unroll
        for (int p = 0; p < 4; p++) {
            int idx = tid + p * 256;
            int r = idx >> 3;
            int c = (idx & 7) * 8;
            cp16(saddr(sa + r * SMST + c), ag + (size_t)r * K + c);
            cp16(saddr(sb + r * SMST + c), bg + (size_t)r * K + c);
        }
    };

    float acc[2][8][4];
    #pragma unroll
    for (int i = 0; i < 2; i++)
        #pragma unroll
        for (int j = 0; j < 8; j++)
            #pragma unroll
            for (int r = 0; r < 4; r++) acc[i][j][r] = 0.f;

    const int nk = K / GBK;

    issue(0, 0); cp_commit();
    issue(1, 1); cp_commit();

    for (int kc = 0; kc < nk; kc++) {
        cp_wait<1>();
        __syncthreads();
        const int s = kc % 3;
        const __half* sa = stageA(s);
        const __half* sb = stageB(s);

        #pragma unroll
        for (int ks = 0; ks < 4; ks++) {
            uint32_t af[2][4];
            #pragma unroll
            for (int mi = 0; mi < 2; mi++) {
                uint32_t a = saddr(&sa[(wm + mi * 16 + (lane & 15)) * SMST + ks * 16 + (lane >> 4) * 8]);
                ldm_x4(af[mi][0], af[mi][1], af[mi][2], af[mi][3], a);
            }
            uint32_t bf[8][2];
            #pragma unroll
            for (int j = 0; j < 4; j++) {
                uint32_t r0, r1, r2, r3;
                uint32_t a = saddr(&sb[(wn + j * 16 + (lane & 15)) * SMST + ks * 16 + (lane >> 4) * 8]);
                ldm_x4(r0, r1, r2, r3, a);
                bf[2 * j + 0][0] = r0; bf[2 * j + 0][1] = r2;
                bf[2 * j + 1][0] = r1; bf[2 * j + 1][1] = r3;
            }
            #pragma unroll
            for (int mi = 0; mi < 2; mi++)
                #pragma unroll
                for (int j = 0; j < 8; j++)
                    mma_f16(acc[mi][j], af[mi], bf[j][0], bf[j][1]);
        }

        if (kc + 2 < nk) issue((kc + 2) % 3, kc + 2);
        cp_commit();
    }

    // ---------------- epilogue: stage C in smem, write coalesced ------------
    cp_wait<0>();
    __syncthreads();

    const int g = lane >> 2, t = lane & 3;
    if (EPI == 0) {
        float* cs = reinterpret_cast<float*>(gsm);
        #pragma unroll
        for (int mi = 0; mi < 2; mi++)
            #pragma unroll
            for (int j = 0; j < 8; j++)
                #pragma unroll
                for (int hh = 0; hh < 2; hh++) {
                    int r = wm + mi * 16 + g + hh * 8;
                    int c = wn + j * 8 + t * 2;
                    cs[r * EPI_F32_STRIDE + c + 0] = acc[mi][j][hh * 2 + 0];
                    cs[r * EPI_F32_STRIDE + c + 1] = acc[mi][j][hh * 2 + 1];
                }
        __syncthreads();
        #pragma unroll
        for (int p = 0; p < 16; p++) {
            int chunk = tid + p * 256;
            int r = chunk >> 5, cc = (chunk & 31) * 4;
            float4 v = *reinterpret_cast<const float4*>(&cs[r * EPI_F32_STRIDE + cc]);
            *reinterpret_cast<float4*>(&outF[(size_t)(m0 + r) * N + n0 + cc]) = v;
        }
    } else {
        __half* cs = gsm;
        #pragma unroll
        for (int mi = 0; mi < 2; mi++)
            #pragma unroll
            for (int j = 0; j < 8; j++)
                #pragma unroll
                for (int hh = 0; hh < 2; hh++) {
                    int r = wm + mi * 16 + g + hh * 8;
                    int c = wn + j * 8 + t * 2;
                    *reinterpret_cast<__half2*>(&cs[r * EPI_F16_STRIDE + c]) =
                        __floats2half2_rn(acc[mi][j][hh * 2 + 0], acc[mi][j][hh * 2 + 1]);
                }
        __syncthreads();
        #pragma unroll
        for (int p = 0; p < 8; p++) {
            int chunk = tid + p * 256;
            int r = chunk >> 4, cc = (chunk & 15) * 8;
            uint4 v = *reinterpret_cast<const uint4*>(&cs[r * EPI_F16_STRIDE + cc]);
            int row = m0 + r;
            int col = n0 + cc;
            int b = row >> 11, s = row & (Ss - 1);
            if (EPI == 3) {  // merged k|v scatter
                if (col < Hh * QHDc) {
                    int h = col / QHDc, d = col - h * QHDc;
                    size_t di = (((size_t)b * Hh + h) * Ss + s) * QHDc + d;
                    *reinterpret_cast<uint4*>(&g_k[di]) = v;
                } else {
                    int c2 = col - Hh * QHDc;
                    int h = c2 >> 7, d = c2 & (DVc - 1);
                    size_t di = (((size_t)b * Hh + h) * Ss + s) * DVc + d;
                    *reinterpret_cast<uint4*>(&g_v[di]) = v;
                }
            } else {  // EPI == 4: merged q|ckv scatter
                if (col < Hh * QHDc) {
                    int h = col / QHDc, d = col - h * QHDc;
                    size_t di = (((size_t)b * Hh + h) * Ss + s) * QHDc + d;
                    *reinterpret_cast<uint4*>(&g_q[di]) = v;
                } else {
                    size_t di = (size_t)row * Rc + (col - Hh * QHDc);
                    *reinterpret_cast<uint4*>(&g_ckv_pre[di]) = v;
                }
            }
        }
    }
}

// ---------------------------------------------------------------------------
// Flash attention (R7/R9 config — measured best): per CTA one (b,h,qtile=64).
// 4 warps, 3 CTAs/SM, synchronous tile loads, no-max exp2 softmax.
// ---------------------------------------------------------------------------
constexpr int QSTRIDE = 200;  // 192 + 8 pad
constexpr int VSTRIDE = 136;  // 128 + 8 pad
constexpr int ATTN_SMEM_BYTES = (64 * QSTRIDE * 2 + 64 * VSTRIDE) * (int)sizeof(__half);

__global__ __launch_bounds__(128, 3) void attn_kernel(const __half* __restrict__ Q,
                                                      const __half* __restrict__ Kt,
                                                      const __half* __restrict__ V,
                                                      __half* __restrict__ Out) {
    extern __shared__ __half sm[];
    __half* sQ = sm;
    __half* sK = sm + 64 * QSTRIDE;
    __half* sV = sm + 2 * 64 * QSTRIDE;

    const int qt = (int)gridDim.x - 1 - (int)blockIdx.x;  // heavy tiles first
    const int h = blockIdx.y, b = blockIdx.z;
    const int tid = threadIdx.x, lane = tid & 31, warp = tid >> 5;
    const int g = lane >> 2, t = lane & 3;
    const int wq = warp * 16;

    const size_t bh = (size_t)b * Hh + h;
    const __half* Qg = Q + (bh * Ss + (size_t)qt * 64) * QHDc;
    const __half* Kg = Kt + bh * Ss * QHDc;
    const __half* Vg = V + bh * Ss * DVc;

    #pragma unroll
    for (int p = 0; p < 12; p++) {
        int idx = tid + p * 128;
        int r = idx / 24, c = (idx % 24) * 8;
        *reinterpret_cast<uint4*>(&sQ[r * QSTRIDE + c]) =
            *reinterpret_cast<const uint4*>(&Qg[(size_t)r * QHDc + c]);
    }

    float o[16][4];
    #pragma unroll
    for (int i = 0; i < 16; i++)
        #pragma unroll
        for (int r = 0; r < 4; r++) o[i][r] = 0.f;
    float lrow[2] = {0.f, 0.f};
    const float scale2 = 0.07216878364870323f * 1.4426950408889634f;  // /sqrt(192)*log2e

    const int nkt = qt + 1;
    for (int kt = 0; kt < nkt; kt++) {
        __syncthreads();
        #pragma unroll
        for (int p = 0; p < 12; p++) {
            int idx = tid + p * 128;
            int r = idx / 24, c = (idx % 24) * 8;
            *reinterpret_cast<uint4*>(&sK[r * QSTRIDE + c]) =
                *reinterpret_cast<const uint4*>(&Kg[((size_t)kt * 64 + r) * QHDc + c]);
        }
        #pragma unroll
        for (int p = 0; p < 8; p++) {
            int idx = tid + p * 128;
            int r = idx >> 4, c = (idx & 15) * 8;
            *reinterpret_cast<uint4*>(&sV[r * VSTRIDE + c]) =
                *reinterpret_cast<const uint4*>(&Vg[((size_t)kt * 64 + r) * DVc + c]);
        }
        __syncthreads();

        float sacc[8][4];
        #pragma unroll
        for (int j = 0; j < 8; j++)
            #pragma unroll
            for (int r = 0; r < 4; r++) sacc[j][r] = 0.f;

        #pragma unroll
        for (int ks = 0; ks < 12; ks++) {
            uint32_t af[4];
            ldm_x4(af[0], af[1], af[2], af[3],
                   saddr(&sQ[(wq + (lane & 15)) * QSTRIDE + ks * 16 + (lane >> 4) * 8]));
            #pragma unroll
            for (int j = 0; j < 4; j++) {
                uint32_t r0, r1, r2, r3;
                ldm_x4(r0, r1, r2, r3,
                       saddr(&sK[(j * 16 + (lane & 15)) * QSTRIDE + ks * 16 + (lane >> 4) * 8]));
                mma_f16(sacc[2 * j + 0], af, r0, r2);
                mma_f16(sacc[2 * j + 1], af, r1, r3);
            }
        }

        const bool diag = (kt == qt);
        #pragma unroll
        for (int hh = 0; hh < 2; hh++) {
            float sum = 0.f;
            #pragma unroll
            for (int j = 0; j < 8; j++) {
                float s0 = sacc[j][hh * 2 + 0] * scale2;
                float s1 = sacc[j][hh * 2 + 1] * scale2;
                if (diag) {
                    int col = kt * 64 + j * 8 + t * 2;
                    int qrow = qt * 64 + wq + g + hh * 8;
                    if (col > qrow)     s0 = -1e30f;
                    if (col + 1 > qrow) s1 = -1e30f;
                }
                float p0 = exp2f(s0);
                float p1 = exp2f(s1);
                sacc[j][hh * 2 + 0] = p0;
                sacc[j][hh * 2 + 1] = p1;
                sum += p0 + p1;
            }
            sum += __shfl_xor_sync(0xffffffffu, sum, 1);
            sum += __shfl_xor_sync(0xffffffffu, sum, 2);
            lrow[hh] += sum;
        }

        uint32_t pa[4][4];
        #pragma unroll
        for (int kk = 0; kk < 4; kk++) {
            pa[kk][0] = packh(sacc[2 * kk][0], sacc[2 * kk][1]);
            pa[kk][1] = packh(sacc[2 * kk][2], sacc[2 * kk][3]);
            pa[kk][2] = packh(sacc[2 * kk + 1][0], sacc[2 * kk + 1][1]);
            pa[kk][3] = packh(sacc[2 * kk + 1][2], sacc[2 * kk + 1][3]);
        }

        #pragma unroll
        for (int kk = 0; kk < 4; kk++) {
            #pragma unroll
            for (int jg = 0; jg < 8; jg++) {
                uint32_t r0, r1, r2, r3;
                ldm_x4t(r0, r1, r2, r3,
                        saddr(&sV[(kk * 16 + (lane & 15)) * VSTRIDE + jg * 16 + (lane >> 4) * 8]));
                mma_f16(o[2 * jg + 0], pa[kk], r0, r1);
                mma_f16(o[2 * jg + 1], pa[kk], r2, r3);
            }
        }
    }

    float inv0 = 1.f / lrow[0];
    float inv1 = 1.f / lrow[1];
    #pragma unroll
    for (int nt = 0; nt < 16; nt++) {
        #pragma unroll
        for (int hh = 0; hh < 2; hh++) {
            float inv = hh ? inv1 : inv0;
            int srow = qt * 64 + wq + g + hh * 8;
            int col = nt * 8 + t * 2;
            __half2 hv = __floats2half2_rn(o[nt][hh * 2] * inv, o[nt][hh * 2 + 1] * inv);
            size_t di = ((size_t)b * Ss + srow) * (Hh * DVc) + (size_t)h * DVc + col;
            *reinterpret_cast<__half2*>(&Out[di]) = hv;
        }
    }
}

// ---------------------------------------------------------------------------
// Host launcher
// ---------------------------------------------------------------------------
static void* symaddr(const void* sym) {
    void* p = nullptr;
    cudaGetSymbolAddress(&p, sym);
    return p;
}

extern "C" void kernel_launch(void* const* d_in, const int* in_sizes, int n_in,
                              void* d_out, int out_size) {
    const float* hidden = (const float*)d_in[0];
    const float* Wq    = (const float*)d_in[3];
    const float* Wkvd  = (const float*)d_in[4];
    const float* normw = (const float*)d_in[5];
    const float* Wkvu  = (const float*)d_in[6];
    const float* Wkvv  = (const float*)d_in[7];
    const float* Wo    = (const float*)d_in[8];
    const float* cosT  = (const float*)d_in[9];
    const float* sinT  = (const float*)d_in[10];
    float* out = (float*)d_out;

    __half* p_hidden = (__half*)symaddr(g_hidden);
    __half* p_Wqd    = (__half*)symaddr(g_Wqd);
    __half* p_Wkvuv  = (__half*)symaddr(g_Wkvuv);
    __half* p_Wo     = (__half*)symaddr(g_Wo);
    __half* p_q      = (__half*)symaddr(g_q);
    __half* p_k      = (__half*)symaddr(g_k);
    __half* p_v      = (__half*)symaddr(g_v);
    __half* p_ckvpre = (__half*)symaddr(g_ckv_pre);
    __half* p_ckv    = (__half*)symaddr(g_ckv);
    __half* p_attn   = (__half*)symaddr(g_attn);

    // launch 0: fused convert
    cvt_all_kernel<<<(N4_TOT + 255) / 256, 256>>>(
        hidden, Wq, Wkvd, Wkvu, Wkvv, Wo,
        p_hidden, p_Wqd, p_Wkvuv, p_Wo);

    cudaFuncSetAttribute(gemm_nt<0>, cudaFuncAttributeMaxDynamicSharedMemorySize, GEMM_SMEM);
    cudaFuncSetAttribute(gemm_nt<3>, cudaFuncAttributeMaxDynamicSharedMemorySize, GEMM_SMEM);
    cudaFuncSetAttribute(gemm_nt<4>, cudaFuncAttributeMaxDynamicSharedMemorySize, GEMM_SMEM);

    // launch 1: merged q|ckv = hidden @ [Wq;Wkv_down]^T (scatter q + ckv_pre)
    gemm_nt<4><<<dim3(NQD / 128, MSc / 128), 256, GEMM_SMEM>>>(
        p_hidden, p_Wqd, nullptr, nullptr, MSc, NQD, HIDc);
    // launch 2: rmsnorm (f16 in -> f16 out)
    rmsnorm_kernel<<<MSc, 128>>>(p_ckvpre, normw, p_ckv);
    // launch 3: merged k|v = ckv @ [Wkv_up;Wkv_v]^T (PROFILED idx 3)
    gemm_nt<3><<<dim3(NKV / 128, MSc / 128), 256, GEMM_SMEM>>>(
        p_ckv, p_Wkvuv, nullptr, nullptr, MSc, NKV, Rc);
    // launch 4: RoPE on q and k (fused)
    {
        int total = 2 * Bb * Hh * Ss * 32;
        rope_kernel<<<(total + 255) / 256, 256>>>(p_q, p_k, cosT, sinT);
    }
    // launch 5: attention (R7 config: 64-row tiles, 128 threads, 3 CTAs/SM)
    cudaFuncSetAttribute(attn_kernel, cudaFuncAttributeMaxDynamicSharedMemorySize,
                         ATTN_SMEM_BYTES);
    attn_kernel<<<dim3(Ss / 64, Hh, Bb), 128, ATTN_SMEM_BYTES>>>(p_q, p_k, p_v, p_attn);
    // launch 6: out = attn @ Wo^T (f32, straight to d_out)
    gemm_nt<0><<<dim3(HIDc / 128, MSc / 128), 256, GEMM_SMEM>>>(
        p_attn, p_Wo, out, nullptr, MSc, HIDc, HIDc);
}

// round 13
// speedup vs baseline: 1.0540x; 1.0160x over previous
#include <cuda_runtime.h>
#include <cuda_fp16.h>
#include <cuda_bf16.h>
#include <cstdint>
#include <cstdio>

#define DEV_INLINE __device__ __forceinline__

// ---------------------------------------------------------------------------
// Problem constants (fixed shapes)
// ---------------------------------------------------------------------------
constexpr int Bb   = 2;
constexpr int Ss   = 2048;
constexpr int HIDc = 2048;
constexpr int Hh   = 16;
constexpr int DNc  = 128;
constexpr int DRc  = 64;
constexpr int DVc  = 128;
constexpr int Rc   = 512;
constexpr int QHDc = DNc + DRc;             // 192
constexpr int MSc  = Bb * Ss;               // 4096 rows
constexpr int NKV  = Hh * QHDc + Hh * DVc;  // 5120 merged k|v cols
constexpr int NQD  = Hh * QHDc + Rc;        // 3584 merged q|ckv cols

// ---------------------------------------------------------------------------
// Scratch (static device globals; no allocation allowed)
// ---------------------------------------------------------------------------
__device__ __half g_hidden[MSc * HIDc];
__device__ __half g_Wqd [NQD * HIDc];         // rows 0..3071 = Wq, 3072..3583 = Wkv_down
__device__ __half g_Wkvuv[NKV * Rc];          // rows 0..3071 = Wkv_up, 3072..5119 = Wkv_v
__device__ __half g_Wo  [HIDc * Hh * DVc];
__device__ __half g_q   [Bb * Hh * Ss * QHDc];
__device__ __half g_k   [Bb * Hh * Ss * QHDc];
__device__ __half g_v   [Bb * Hh * Ss * DVc];
__device__ __half g_ckv_pre[MSc * Rc];        // pre-norm ckv (f16)
__device__ __half g_ckv [MSc * Rc];
__device__ __half g_attn[MSc * Hh * DVc];

// ---------------------------------------------------------------------------
// PTX helpers
// ---------------------------------------------------------------------------
DEV_INLINE uint32_t saddr(const void* p) {
    return (uint32_t)__cvta_generic_to_shared(p);
}
DEV_INLINE void ldm_x4(uint32_t& r0, uint32_t& r1, uint32_t& r2, uint32_t& r3, uint32_t a) {
    asm volatile("ldmatrix.sync.aligned.m8n8.x4.shared.b16 {%0,%1,%2,%3}, [%4];\n"
                 : "=r"(r0), "=r"(r1), "=r"(r2), "=r"(r3) : "r"(a));
}
DEV_INLINE void ldm_x4t(uint32_t& r0, uint32_t& r1, uint32_t& r2, uint32_t& r3, uint32_t a) {
    asm volatile("ldmatrix.sync.aligned.m8n8.x4.trans.shared.b16 {%0,%1,%2,%3}, [%4];\n"
                 : "=r"(r0), "=r"(r1), "=r"(r2), "=r"(r3) : "r"(a));
}
DEV_INLINE void mma_f16(float c[4], const uint32_t a[4], const uint32_t b0, const uint32_t b1) {
    asm volatile(
        "mma.sync.aligned.m16n8k16.row.col.f32.f16.f16.f32 "
        "{%0,%1,%2,%3},{%4,%5,%6,%7},{%8,%9},{%0,%1,%2,%3};\n"
        : "+f"(c[0]), "+f"(c[1]), "+f"(c[2]), "+f"(c[3])
        : "r"(a[0]), "r"(a[1]), "r"(a[2]), "r"(a[3]), "r"(b0), "r"(b1));
}
DEV_INLINE uint32_t packh(float a, float b) {
    __half2 h = __floats2half2_rn(a, b);
    return *reinterpret_cast<uint32_t*>(&h);
}

// cp.async helpers
DEV_INLINE void cp16(uint32_t dst_smem, const void* src) {
    asm volatile("cp.async.cg.shared.global [%0], [%1], 16;\n"
                 :: "r"(dst_smem), "l"(src));
}
DEV_INLINE void cp_commit() {
    asm volatile("cp.async.commit_group;\n" ::: "memory");
}
template <int N>
DEV_INLINE void cp_wait() {
    asm volatile("cp.async.wait_group %0;\n" :: "n"(N) : "memory");
}

// ---------------------------------------------------------------------------
// Fused f32 -> f16 convert for all 6 tensors (one launch).
// Wq/Wkv_down merge into g_Wqd; Wkv_up/Wkv_v merge into g_Wkvuv.
// ---------------------------------------------------------------------------
constexpr int N4_HID  = MSc * HIDc / 4;
constexpr int N4_WQ   = Hh * QHDc * HIDc / 4;
constexpr int N4_WKVD = Rc * HIDc / 4;
constexpr int N4_WKVU = Hh * QHDc * Rc / 4;
constexpr int N4_WKVV = Hh * DVc * Rc / 4;
constexpr int N4_WO   = HIDc * Hh * DVc / 4;
constexpr int N4_C0 = N4_HID;
constexpr int N4_C1 = N4_C0 + N4_WQ;
constexpr int N4_C2 = N4_C1 + N4_WKVD;
constexpr int N4_C3 = N4_C2 + N4_WKVU;
constexpr int N4_C4 = N4_C3 + N4_WKVV;
constexpr int N4_TOT = N4_C4 + N4_WO;

__global__ __launch_bounds__(256) void cvt_all_kernel(
    const float* __restrict__ hid, const float* __restrict__ wq,
    const float* __restrict__ wkvd, const float* __restrict__ wkvu,
    const float* __restrict__ wkvv, const float* __restrict__ wo,
    __half* __restrict__ d_hid, __half* __restrict__ d_wqd,
    __half* __restrict__ d_wkvuv, __half* __restrict__ d_wo) {
    int i = blockIdx.x * blockDim.x + threadIdx.x;
    if (i >= N4_TOT) return;
    const float* src;
    __half* dst;
    int j;
    if (i < N4_C0)      { src = hid;  dst = d_hid;  j = i; }
    else if (i < N4_C1) { src = wq;   dst = d_wqd;  j = i - N4_C0; }
    else if (i < N4_C2) { src = wkvd; dst = d_wqd + Hh * QHDc * HIDc; j = i - N4_C1; }
    else if (i < N4_C3) { src = wkvu; dst = d_wkvuv; j = i - N4_C2; }
    else if (i < N4_C4) { src = wkvv; dst = d_wkvuv + Hh * QHDc * Rc; j = i - N4_C3; }
    else                { src = wo;   dst = d_wo;   j = i - N4_C4; }
    float4 v = reinterpret_cast<const float4*>(src)[j];
    __half2 a = __floats2half2_rn(v.x, v.y);
    __half2 b = __floats2half2_rn(v.z, v.w);
    reinterpret_cast<__half2*>(dst)[2 * j + 0] = a;
    reinterpret_cast<__half2*>(dst)[2 * j + 1] = b;
}

// ---------------------------------------------------------------------------
// RMSNorm over R=512, f16 in -> f16 out (square-sum in f32)
// ---------------------------------------------------------------------------
__global__ __launch_bounds__(128) void rmsnorm_kernel(const __half* __restrict__ raw,
                                                      const float* __restrict__ w,
                                                      __half* __restrict__ out) {
    int row = blockIdx.x;
    const uint2* r2 = reinterpret_cast<const uint2*>(raw + (size_t)row * Rc);
    uint2 u = r2[threadIdx.x];
    __half2 h01 = *reinterpret_cast<__half2*>(&u.x);
    __half2 h23 = *reinterpret_cast<__half2*>(&u.y);
    float x0 = __low2float(h01), x1 = __high2float(h01);
    float x2 = __low2float(h23), x3 = __high2float(h23);
    float ss = x0 * x0 + x1 * x1 + x2 * x2 + x3 * x3;
    #pragma unroll
    for (int o = 16; o; o >>= 1) ss += __shfl_xor_sync(0xffffffffu, ss, o);
    __shared__ float red[4];
    if ((threadIdx.x & 31) == 0) red[threadIdx.x >> 5] = ss;
    __syncthreads();
    float tot = red[0] + red[1] + red[2] + red[3];
    float inv = rsqrtf(tot * (1.0f / (float)Rc) + 1e-5f);
    float4 wv = reinterpret_cast<const float4*>(w)[threadIdx.x];
    __half2 o0 = __floats2half2_rn(x0 * inv * wv.x, x1 * inv * wv.y);
    __half2 o1 = __floats2half2_rn(x2 * inv * wv.z, x3 * inv * wv.w);
    __half2* op = reinterpret_cast<__half2*>(out + (size_t)row * Rc + threadIdx.x * 4);
    op[0] = o0;
    op[1] = o1;
}

// ---------------------------------------------------------------------------
// RoPE in-place on q AND k (both [B,H,S,QHD] f16), rope dims [128,192)
// ---------------------------------------------------------------------------
__global__ __launch_bounds__(256) void rope_kernel(__half* __restrict__ Xq,
                                                   __half* __restrict__ Xk,
                                                   const float* __restrict__ cosT,
                                                   const float* __restrict__ sinT) {
    int idx = blockIdx.x * blockDim.x + threadIdx.x;
    int j = idx & 31;
    int row = idx >> 5;
    const int nrows = Bb * Hh * Ss;
    if (row >= 2 * nrows) return;
    __half* X = (row < nrows) ? Xq : Xk;
    if (row >= nrows) row -= nrows;
    int s = row & (Ss - 1);
    __half* base = X + (size_t)row * QHDc + DNc;
    float x1 = __half2float(base[j]);
    float x2 = __half2float(base[j + 32]);
    float c1 = cosT[s * DRc + j];
    float s1 = sinT[s * DRc + j];
    float c2 = cosT[s * DRc + 32 + j];
    float s2 = sinT[s * DRc + 32 + j];
    base[j]      = __float2half_rn(x1 * c1 - x2 * s1);
    base[j + 32] = __float2half_rn(x2 * c2 + x1 * s2);
}

// ---------------------------------------------------------------------------
// NT GEMM, cp.async 3-stage pipeline, BK=64, coalesced smem-staged epilogue.
// EPI: 0 = f32 plain
//      3 = merged k|v scatter: col<3072 -> g_k, else -> g_v
//      4 = merged q|ckv scatter: col<3072 -> g_q, else -> g_ckv_pre (f16 linear)
// ---------------------------------------------------------------------------
constexpr int GBK      = 64;
constexpr int SMST     = 72;
constexpr int GSTAGES  = 3;
constexpr int STAGE_HALVES = 128 * SMST;
constexpr int GEMM_SMEM = GSTAGES * 2 * STAGE_HALVES * (int)sizeof(__half);  // 110592
constexpr int EPI_F32_STRIDE = 132;
constexpr int EPI_F16_STRIDE = 136;
static_assert(128 * EPI_F32_STRIDE * 4 <= GEMM_SMEM, "f32 stage fits");

template <int EPI>
__global__ __launch_bounds__(256, 2) void gemm_nt(const __half* __restrict__ A,
                                                  const __half* __restrict__ Bw,
                                                  float* __restrict__ outF,
                                                  __half* __restrict__ outH,
                                                  int M, int N, int K) {
    extern __shared__ __half gsm[];

    const int tid = threadIdx.x;
    const int lane = tid & 31, warp = tid >> 5;
    const int wm = (warp & 3) * 32, wn = (warp >> 2) * 64;
    const int m0 = blockIdx.y * 128, n0 = blockIdx.x * 128;

    const __half* Ag = A + (size_t)m0 * K;
    const __half* Bg = Bw + (size_t)n0 * K;

    auto stageA = [&](int s) -> __half* { return gsm + s * 2 * STAGE_HALVES; };
    auto stageB = [&](int s) -> __half* { return gsm + s * 2 * STAGE_HALVES + STAGE_HALVES; };

    auto issue = [&](int s, int kc) {
        __half* sa = stageA(s);
        __half* sb = stageB(s);
        const __half* ag = Ag + (size_t)kc * GBK;
        const __half* bg = Bg + (size_t)kc * GBK;
        #pragma unroll
        for (int p = 0; p < 4; p++) {
            int idx = tid + p * 256;
            int r = idx >> 3;
            int c = (idx & 7) * 8;
            cp16(saddr(sa + r * SMST + c), ag + (size_t)r * K + c);
            cp16(saddr(sb + r * SMST + c), bg + (size_t)r * K + c);
        }
    };

    float acc[2][8][4];
    #pragma unroll
    for (int i = 0; i < 2; i++)
        #pragma unroll
        for (int j = 0; j < 8; j++)
            #pragma unroll
            for (int r = 0; r < 4; r++) acc[i][j][r] = 0.f;

    const int nk = K / GBK;

    issue(0, 0); cp_commit();
    issue(1, 1); cp_commit();

    for (int kc = 0; kc < nk; kc++) {
        cp_wait<1>();
        __syncthreads();
        const int s = kc % 3;
        const __half* sa = stageA(s);
        const __half* sb = stageB(s);

        #pragma unroll
        for (int ks = 0; ks < 4; ks++) {
            uint32_t af[2][4];
            #pragma unroll
            for (int mi = 0; mi < 2; mi++) {
                uint32_t a = saddr(&sa[(wm + mi * 16 + (lane & 15)) * SMST + ks * 16 + (lane >> 4) * 8]);
                ldm_x4(af[mi][0], af[mi][1], af[mi][2], af[mi][3], a);
            }
            uint32_t bf[8][2];
            #pragma unroll
            for (int j = 0; j < 4; j++) {
                uint32_t r0, r1, r2, r3;
                uint32_t a = saddr(&sb[(wn + j * 16 + (lane & 15)) * SMST + ks * 16 + (lane >> 4) * 8]);
                ldm_x4(r0, r1, r2, r3, a);
                bf[2 * j + 0][0] = r0; bf[2 * j + 0][1] = r2;
                bf[2 * j + 1][0] = r1; bf[2 * j + 1][1] = r3;
            }
            #pragma unroll
            for (int mi = 0; mi < 2; mi++)
                #pragma unroll
                for (int j = 0; j < 8; j++)
                    mma_f16(acc[mi][j], af[mi], bf[j][0], bf[j][1]);
        }

        if (kc + 2 < nk) issue((kc + 2) % 3, kc + 2);
        cp_commit();
    }

    // ---------------- epilogue: stage C in smem, write coalesced ------------
    cp_wait<0>();
    __syncthreads();

    const int g = lane >> 2, t = lane & 3;
    if (EPI == 0) {
        float* cs = reinterpret_cast<float*>(gsm);
        #pragma unroll
        for (int mi = 0; mi < 2; mi++)
            #pragma unroll
            for (int j = 0; j < 8; j++)
                #pragma unroll
                for (int hh = 0; hh < 2; hh++) {
                    int r = wm + mi * 16 + g + hh * 8;
                    int c = wn + j * 8 + t * 2;
                    cs[r * EPI_F32_STRIDE + c + 0] = acc[mi][j][hh * 2 + 0];
                    cs[r * EPI_F32_STRIDE + c + 1] = acc[mi][j][hh * 2 + 1];
                }
        __syncthreads();
        #pragma unroll
        for (int p = 0; p < 16; p++) {
            int chunk = tid + p * 256;
            int r = chunk >> 5, cc = (chunk & 31) * 4;
            float4 v = *reinterpret_cast<const float4*>(&cs[r * EPI_F32_STRIDE + cc]);
            *reinterpret_cast<float4*>(&outF[(size_t)(m0 + r) * N + n0 + cc]) = v;
        }
    } else {
        __half* cs = gsm;
        #pragma unroll
        for (int mi = 0; mi < 2; mi++)
            #pragma unroll
            for (int j = 0; j < 8; j++)
                #pragma unroll
                for (int hh = 0; hh < 2; hh++) {
                    int r = wm + mi * 16 + g + hh * 8;
                    int c = wn + j * 8 + t * 2;
                    *reinterpret_cast<__half2*>(&cs[r * EPI_F16_STRIDE + c]) =
                        __floats2half2_rn(acc[mi][j][hh * 2 + 0], acc[mi][j][hh * 2 + 1]);
                }
        __syncthreads();
        #pragma unroll
        for (int p = 0; p < 8; p++) {
            int chunk = tid + p * 256;
            int r = chunk >> 4, cc = (chunk & 15) * 8;
            uint4 v = *reinterpret_cast<const uint4*>(&cs[r * EPI_F16_STRIDE + cc]);
            int row = m0 + r;
            int col = n0 + cc;
            int b = row >> 11, s = row & (Ss - 1);
            if (EPI == 3) {  // merged k|v scatter
                if (col < Hh * QHDc) {
                    int h = col / QHDc, d = col - h * QHDc;
                    size_t di = (((size_t)b * Hh + h) * Ss + s) * QHDc + d;
                    *reinterpret_cast<uint4*>(&g_k[di]) = v;
                } else {
                    int c2 = col - Hh * QHDc;
                    int h = c2 >> 7, d = c2 & (DVc - 1);
                    size_t di = (((size_t)b * Hh + h) * Ss + s) * DVc + d;
                    *reinterpret_cast<uint4*>(&g_v[di]) = v;
                }
            } else {  // EPI == 4: merged q|ckv scatter
                if (col < Hh * QHDc) {
                    int h = col / QHDc, d = col - h * QHDc;
                    size_t di = (((size_t)b * Hh + h) * Ss + s) * QHDc + d;
                    *reinterpret_cast<uint4*>(&g_q[di]) = v;
                } else {
                    size_t di = (size_t)row * Rc + (col - Hh * QHDc);
                    *reinterpret_cast<uint4*>(&g_ckv_pre[di]) = v;
                }
            }
        }
    }
}

// ---------------------------------------------------------------------------
// Flash attention: per CTA one (b,h,qtile=64 rows). 4 warps, 3 CTAs/SM.
// K and V tiles loaded via SPLIT cp.async groups: K group waited before QK,
// V group waited only before PV (V load hidden under QK mma). Same smem and
// registers as the R7/R12 config. No-max exp2 softmax.
// ---------------------------------------------------------------------------
constexpr int QSTRIDE = 200;  // 192 + 8 pad
constexpr int VSTRIDE = 136;  // 128 + 8 pad
constexpr int ATTN_SMEM_BYTES = (64 * QSTRIDE * 2 + 64 * VSTRIDE) * (int)sizeof(__half);

__global__ __launch_bounds__(128, 3) void attn_kernel(const __half* __restrict__ Q,
                                                      const __half* __restrict__ Kt,
                                                      const __half* __restrict__ V,
                                                      __half* __restrict__ Out) {
    extern __shared__ __half sm[];
    __half* sQ = sm;
    __half* sK = sm + 64 * QSTRIDE;
    __half* sV = sm + 2 * 64 * QSTRIDE;

    const int qt = (int)gridDim.x - 1 - (int)blockIdx.x;  // heavy tiles first
    const int h = blockIdx.y, b = blockIdx.z;
    const int tid = threadIdx.x, lane = tid & 31, warp = tid >> 5;
    const int g = lane >> 2, t = lane & 3;
    const int wq = warp * 16;

    const size_t bh = (size_t)b * Hh + h;
    const __half* Qg = Q + (bh * Ss + (size_t)qt * 64) * QHDc;
    const __half* Kg = Kt + bh * Ss * QHDc;
    const __half* Vg = V + bh * Ss * DVc;

    #pragma unroll
    for (int p = 0; p < 12; p++) {
        int idx = tid + p * 128;
        int r = idx / 24, c = (idx % 24) * 8;
        *reinterpret_cast<uint4*>(&sQ[r * QSTRIDE + c]) =
            *reinterpret_cast<const uint4*>(&Qg[(size_t)r * QHDc + c]);
    }

    float o[16][4];
    #pragma unroll
    for (int i = 0; i < 16; i++)
        #pragma unroll
        for (int r = 0; r < 4; r++) o[i][r] = 0.f;
    float lrow[2] = {0.f, 0.f};
    const float scale2 = 0.07216878364870323f * 1.4426950408889634f;  // /sqrt(192)*log2e

    const int nkt = qt + 1;
    for (int kt = 0; kt < nkt; kt++) {
        __syncthreads();  // previous QK (sK) and PV (sV) readers done
        // group A: K tile (12 x 16B chunks per thread)
        #pragma unroll
        for (int p = 0; p < 12; p++) {
            int idx = tid + p * 128;
            int r = idx / 24, c = (idx % 24) * 8;
            cp16(saddr(&sK[r * QSTRIDE + c]), &Kg[((size_t)kt * 64 + r) * QHDc + c]);
        }
        cp_commit();
        // group B: V tile (8 x 16B chunks per thread)
        #pragma unroll
        for (int p = 0; p < 8; p++) {
            int idx = tid + p * 128;
            int r = idx >> 4, c = (idx & 15) * 8;
            cp16(saddr(&sV[r * VSTRIDE + c]), &Vg[((size_t)kt * 64 + r) * DVc + c]);
        }
        cp_commit();
        cp_wait<1>();     // K group done; V may still be in flight
        __syncthreads();

        float sacc[8][4];
        #pragma unroll
        for (int j = 0; j < 8; j++)
            #pragma unroll
            for (int r = 0; r < 4; r++) sacc[j][r] = 0.f;

        #pragma unroll
        for (int ks = 0; ks < 12; ks++) {
            uint32_t af[4];
            ldm_x4(af[0], af[1], af[2], af[3],
                   saddr(&sQ[(wq + (lane & 15)) * QSTRIDE + ks * 16 + (lane >> 4) * 8]));
            #pragma unroll
            for (int j = 0; j < 4; j++) {
                uint32_t r0, r1, r2, r3;
                ldm_x4(r0, r1, r2, r3,
                       saddr(&sK[(j * 16 + (lane & 15)) * QSTRIDE + ks * 16 + (lane >> 4) * 8]));
                mma_f16(sacc[2 * j + 0], af, r0, r2);
                mma_f16(sacc[2 * j + 1], af, r1, r3);
            }
        }

        const bool diag = (kt == qt);
        #pragma unroll
        for (int hh = 0; hh < 2; hh++) {
            float sum = 0.f;
            #pragma unroll
            for (int j = 0; j < 8; j++) {
                float s0 = sacc[j][hh * 2 + 0] * scale2;
                float s1 = sacc[j][hh * 2 + 1] * scale2;
                if (diag) {
                    int col = kt * 64 + j * 8 + t * 2;
                    int qrow = qt * 64 + wq + g + hh * 8;
                    if (col > qrow)     s0 = -1e30f;
                    if (col + 1 > qrow) s1 = -1e30f;
                }
                float p0 = exp2f(s0);
                float p1 = exp2f(s1);
                sacc[j][hh * 2 + 0] = p0;
                sacc[j][hh * 2 + 1] = p1;
                sum += p0 + p1;
            }
            sum += __shfl_xor_sync(0xffffffffu, sum, 1);
            sum += __shfl_xor_sync(0xffffffffu, sum, 2);
            lrow[hh] += sum;
        }

        uint32_t pa[4][4];
        #pragma unroll
        for (int kk = 0; kk < 4; kk++) {
            pa[kk][0] = packh(sacc[2 * kk][0], sacc[2 * kk][1]);
            pa[kk][1] = packh(sacc[2 * kk][2], sacc[2 * kk][3]);
            pa[kk][2] = packh(sacc[2 * kk + 1][0], sacc[2 * kk + 1][1]);
            pa[kk][3] = packh(sacc[2 * kk + 1][2], sacc[2 * kk + 1][3]);
        }

        cp_wait<0>();     // V group done (loaded under QK + softmax)
        __syncthreads();

        #pragma unroll
        for (int kk = 0; kk < 4; kk++) {
            #pragma unroll
            for (int jg = 0; jg < 8; jg++) {
                uint32_t r0, r1, r2, r3;
                ldm_x4t(r0, r1, r2, r3,
                        saddr(&sV[(kk * 16 + (lane & 15)) * VSTRIDE + jg * 16 + (lane >> 4) * 8]));
                mma_f16(o[2 * jg + 0], pa[kk], r0, r1);
                mma_f16(o[2 * jg + 1], pa[kk], r2, r3);
            }
        }
    }

    float inv0 = 1.f / lrow[0];
    float inv1 = 1.f / lrow[1];
    #pragma unroll
    for (int nt = 0; nt < 16; nt++) {
        #pragma unroll
        for (int hh = 0; hh < 2; hh++) {
            float inv = hh ? inv1 : inv0;
            int srow = qt * 64 + wq + g + hh * 8;
            int col = nt * 8 + t * 2;
            __half2 hv = __floats2half2_rn(o[nt][hh * 2] * inv, o[nt][hh * 2 + 1] * inv);
            size_t di = ((size_t)b * Ss + srow) * (Hh * DVc) + (size_t)h * DVc + col;
            *reinterpret_cast<__half2*>(&Out[di]) = hv;
        }
    }
}

// ---------------------------------------------------------------------------
// Host launcher
// ---------------------------------------------------------------------------
static void* symaddr(const void* sym) {
    void* p = nullptr;
    cudaGetSymbolAddress(&p, sym);
    return p;
}

extern "C" void kernel_launch(void* const* d_in, const int* in_sizes, int n_in,
                              void* d_out, int out_size) {
    const float* hidden = (const float*)d_in[0];
    const float* Wq    = (const float*)d_in[3];
    const float* Wkvd  = (const float*)d_in[4];
    const float* normw = (const float*)d_in[5];
    const float* Wkvu  = (const float*)d_in[6];
    const float* Wkvv  = (const float*)d_in[7];
    const float* Wo    = (const float*)d_in[8];
    const float* cosT  = (const float*)d_in[9];
    const float* sinT  = (const float*)d_in[10];
    float* out = (float*)d_out;

    __half* p_hidden = (__half*)symaddr(g_hidden);
    __half* p_Wqd    = (__half*)symaddr(g_Wqd);
    __half* p_Wkvuv  = (__half*)symaddr(g_Wkvuv);
    __half* p_Wo     = (__half*)symaddr(g_Wo);
    __half* p_q      = (__half*)symaddr(g_q);
    __half* p_k      = (__half*)symaddr(g_k);
    __half* p_v      = (__half*)symaddr(g_v);
    __half* p_ckvpre = (__half*)symaddr(g_ckv_pre);
    __half* p_ckv    = (__half*)symaddr(g_ckv);
    __half* p_attn   = (__half*)symaddr(g_attn);

    // launch 0: fused convert
    cvt_all_kernel<<<(N4_TOT + 255) / 256, 256>>>(
        hidden, Wq, Wkvd, Wkvu, Wkvv, Wo,
        p_hidden, p_Wqd, p_Wkvuv, p_Wo);

    cudaFuncSetAttribute(gemm_nt<0>, cudaFuncAttributeMaxDynamicSharedMemorySize, GEMM_SMEM);
    cudaFuncSetAttribute(gemm_nt<3>, cudaFuncAttributeMaxDynamicSharedMemorySize, GEMM_SMEM);
    cudaFuncSetAttribute(gemm_nt<4>, cudaFuncAttributeMaxDynamicSharedMemorySize, GEMM_SMEM);

    // launch 1: merged q|ckv = hidden @ [Wq;Wkv_down]^T (scatter q + ckv_pre)
    gemm_nt<4><<<dim3(NQD / 128, MSc / 128), 256, GEMM_SMEM>>>(
        p_hidden, p_Wqd, nullptr, nullptr, MSc, NQD, HIDc);
    // launch 2: rmsnorm (f16 in -> f16 out)
    rmsnorm_kernel<<<MSc, 128>>>(p_ckvpre, normw, p_ckv);
    // launch 3: merged k|v = ckv @ [Wkv_up;Wkv_v]^T (PROFILED idx 3, control)
    gemm_nt<3><<<dim3(NKV / 128, MSc / 128), 256, GEMM_SMEM>>>(
        p_ckv, p_Wkvuv, nullptr, nullptr, MSc, NKV, Rc);
    // launch 4: RoPE on q and k (fused)
    {
        int total = 2 * Bb * Hh * Ss * 32;
        rope_kernel<<<(total + 255) / 256, 256>>>(p_q, p_k, cosT, sinT);
    }
    // launch 5: attention (64-row tiles, 3 CTAs/SM, split cp.async K/V groups)
    cudaFuncSetAttribute(attn_kernel, cudaFuncAttributeMaxDynamicSharedMemorySize,
                         ATTN_SMEM_BYTES);
    attn_kernel<<<dim3(Ss / 64, Hh, Bb), 128, ATTN_SMEM_BYTES>>>(p_q, p_k, p_v, p_attn);
    // launch 6: out = attn @ Wo^T (f32, straight to d_out)
    gemm_nt<0><<<dim3(HIDc / 128, MSc / 128), 256, GEMM_SMEM>>>(
        p_attn, p_Wo, out, nullptr, MSc, HIDc, HIDc);
}

// round 14
// speedup vs baseline: 1.0788x; 1.0235x over previous
#include <cuda_runtime.h>
#include <cuda_fp16.h>
#include <cuda_bf16.h>
#include <cstdint>
#include <cstdio>

#define DEV_INLINE __device__ __forceinline__

// ---------------------------------------------------------------------------
// Problem constants (fixed shapes)
// ---------------------------------------------------------------------------
constexpr int Bb   = 2;
constexpr int Ss   = 2048;
constexpr int HIDc = 2048;
constexpr int Hh   = 16;
constexpr int DNc  = 128;
constexpr int DRc  = 64;
constexpr int DVc  = 128;
constexpr int Rc   = 512;
constexpr int QHDc = DNc + DRc;             // 192
constexpr int MSc  = Bb * Ss;               // 4096 rows
constexpr int NKV  = Hh * QHDc + Hh * DVc;  // 5120 merged k|v cols
constexpr int NQD  = Hh * QHDc + Rc;        // 3584 merged q|ckv cols

// ---------------------------------------------------------------------------
// Scratch (static device globals; no allocation allowed)
// ---------------------------------------------------------------------------
__device__ __half g_hidden[MSc * HIDc];
__device__ __half g_Wqd [NQD * HIDc];         // rows 0..3071 = Wq, 3072..3583 = Wkv_down
__device__ __half g_Wkvuv[NKV * Rc];          // rows 0..3071 = Wkv_up, 3072..5119 = Wkv_v
__device__ __half g_Wo  [HIDc * Hh * DVc];
__device__ __half g_q   [Bb * Hh * Ss * QHDc];
__device__ __half g_k   [Bb * Hh * Ss * QHDc];
__device__ __half g_v   [Bb * Hh * Ss * DVc];
__device__ __half g_ckv_pre[MSc * Rc];        // pre-norm ckv (f16)
__device__ __half g_ckv [MSc * Rc];
__device__ __half g_attn[MSc * Hh * DVc];

// ---------------------------------------------------------------------------
// PTX helpers
// ---------------------------------------------------------------------------
DEV_INLINE uint32_t saddr(const void* p) {
    return (uint32_t)__cvta_generic_to_shared(p);
}
DEV_INLINE void ldm_x4(uint32_t& r0, uint32_t& r1, uint32_t& r2, uint32_t& r3, uint32_t a) {
    asm volatile("ldmatrix.sync.aligned.m8n8.x4.shared.b16 {%0,%1,%2,%3}, [%4];\n"
                 : "=r"(r0), "=r"(r1), "=r"(r2), "=r"(r3) : "r"(a));
}
DEV_INLINE void ldm_x4t(uint32_t& r0, uint32_t& r1, uint32_t& r2, uint32_t& r3, uint32_t a) {
    asm volatile("ldmatrix.sync.aligned.m8n8.x4.trans.shared.b16 {%0,%1,%2,%3}, [%4];\n"
                 : "=r"(r0), "=r"(r1), "=r"(r2), "=r"(r3) : "r"(a));
}
DEV_INLINE void mma_f16(float c[4], const uint32_t a[4], const uint32_t b0, const uint32_t b1) {
    asm volatile(
        "mma.sync.aligned.m16n8k16.row.col.f32.f16.f16.f32 "
        "{%0,%1,%2,%3},{%4,%5,%6,%7},{%8,%9},{%0,%1,%2,%3};\n"
        : "+f"(c[0]), "+f"(c[1]), "+f"(c[2]), "+f"(c[3])
        : "r"(a[0]), "r"(a[1]), "r"(a[2]), "r"(a[3]), "r"(b0), "r"(b1));
}
DEV_INLINE uint32_t packh(float a, float b) {
    __half2 h = __floats2half2_rn(a, b);
    return *reinterpret_cast<uint32_t*>(&h);
}

// cp.async helpers
DEV_INLINE void cp16(uint32_t dst_smem, const void* src) {
    asm volatile("cp.async.cg.shared.global [%0], [%1], 16;\n"
                 :: "r"(dst_smem), "l"(src));
}
DEV_INLINE void cp_commit() {
    asm volatile("cp.async.commit_group;\n" ::: "memory");
}
template <int N>
DEV_INLINE void cp_wait() {
    asm volatile("cp.async.wait_group %0;\n" :: "n"(N) : "memory");
}

// ---------------------------------------------------------------------------
// Fused f32 -> f16 convert for all 6 tensors (one launch).
// Wq/Wkv_down merge into g_Wqd; Wkv_up/Wkv_v merge into g_Wkvuv.
// ---------------------------------------------------------------------------
constexpr int N4_HID  = MSc * HIDc / 4;
constexpr int N4_WQ   = Hh * QHDc * HIDc / 4;
constexpr int N4_WKVD = Rc * HIDc / 4;
constexpr int N4_WKVU = Hh * QHDc * Rc / 4;
constexpr int N4_WKVV = Hh * DVc * Rc / 4;
constexpr int N4_WO   = HIDc * Hh * DVc / 4;
constexpr int N4_C0 = N4_HID;
constexpr int N4_C1 = N4_C0 + N4_WQ;
constexpr int N4_C2 = N4_C1 + N4_WKVD;
constexpr int N4_C3 = N4_C2 + N4_WKVU;
constexpr int N4_C4 = N4_C3 + N4_WKVV;
constexpr int N4_TOT = N4_C4 + N4_WO;

__global__ __launch_bounds__(256) void cvt_all_kernel(
    const float* __restrict__ hid, const float* __restrict__ wq,
    const float* __restrict__ wkvd, const float* __restrict__ wkvu,
    const float* __restrict__ wkvv, const float* __restrict__ wo,
    __half* __restrict__ d_hid, __half* __restrict__ d_wqd,
    __half* __restrict__ d_wkvuv, __half* __restrict__ d_wo) {
    int i = blockIdx.x * blockDim.x + threadIdx.x;
    if (i >= N4_TOT) return;
    const float* src;
    __half* dst;
    int j;
    if (i < N4_C0)      { src = hid;  dst = d_hid;  j = i; }
    else if (i < N4_C1) { src = wq;   dst = d_wqd;  j = i - N4_C0; }
    else if (i < N4_C2) { src = wkvd; dst = d_wqd + Hh * QHDc * HIDc; j = i - N4_C1; }
    else if (i < N4_C3) { src = wkvu; dst = d_wkvuv; j = i - N4_C2; }
    else if (i < N4_C4) { src = wkvv; dst = d_wkvuv + Hh * QHDc * Rc; j = i - N4_C3; }
    else                { src = wo;   dst = d_wo;   j = i - N4_C4; }
    float4 v = reinterpret_cast<const float4*>(src)[j];
    __half2 a = __floats2half2_rn(v.x, v.y);
    __half2 b = __floats2half2_rn(v.z, v.w);
    reinterpret_cast<__half2*>(dst)[2 * j + 0] = a;
    reinterpret_cast<__half2*>(dst)[2 * j + 1] = b;
}

// ---------------------------------------------------------------------------
// RMSNorm over R=512, f16 in -> f16 out (square-sum in f32)
// ---------------------------------------------------------------------------
__global__ __launch_bounds__(128) void rmsnorm_kernel(const __half* __restrict__ raw,
                                                      const float* __restrict__ w,
                                                      __half* __restrict__ out) {
    int row = blockIdx.x;
    const uint2* r2 = reinterpret_cast<const uint2*>(raw + (size_t)row * Rc);
    uint2 u = r2[threadIdx.x];
    __half2 h01 = *reinterpret_cast<__half2*>(&u.x);
    __half2 h23 = *reinterpret_cast<__half2*>(&u.y);
    float x0 = __low2float(h01), x1 = __high2float(h01);
    float x2 = __low2float(h23), x3 = __high2float(h23);
    float ss = x0 * x0 + x1 * x1 + x2 * x2 + x3 * x3;
    #pragma unroll
    for (int o = 16; o; o >>= 1) ss += __shfl_xor_sync(0xffffffffu, ss, o);
    __shared__ float red[4];
    if ((threadIdx.x & 31) == 0) red[threadIdx.x >> 5] = ss;
    __syncthreads();
    float tot = red[0] + red[1] + red[2] + red[3];
    float inv = rsqrtf(tot * (1.0f / (float)Rc) + 1e-5f);
    float4 wv = reinterpret_cast<const float4*>(w)[threadIdx.x];
    __half2 o0 = __floats2half2_rn(x0 * inv * wv.x, x1 * inv * wv.y);
    __half2 o1 = __floats2half2_rn(x2 * inv * wv.z, x3 * inv * wv.w);
    __half2* op = reinterpret_cast<__half2*>(out + (size_t)row * Rc + threadIdx.x * 4);
    op[0] = o0;
    op[1] = o1;
}

// ---------------------------------------------------------------------------
// RoPE in-place on q AND k (both [B,H,S,QHD] f16), rope dims [128,192)
// ---------------------------------------------------------------------------
__global__ __launch_bounds__(256) void rope_kernel(__half* __restrict__ Xq,
                                                   __half* __restrict__ Xk,
                                                   const float* __restrict__ cosT,
                                                   const float* __restrict__ sinT) {
    int idx = blockIdx.x * blockDim.x + threadIdx.x;
    int j = idx & 31;
    int row = idx >> 5;
    const int nrows = Bb * Hh * Ss;
    if (row >= 2 * nrows) return;
    __half* X = (row < nrows) ? Xq : Xk;
    if (row >= nrows) row -= nrows;
    int s = row & (Ss - 1);
    __half* base = X + (size_t)row * QHDc + DNc;
    float x1 = __half2float(base[j]);
    float x2 = __half2float(base[j + 32]);
    float c1 = cosT[s * DRc + j];
    float s1 = sinT[s * DRc + j];
    float c2 = cosT[s * DRc + 32 + j];
    float s2 = sinT[s * DRc + 32 + j];
    base[j]      = __float2half_rn(x1 * c1 - x2 * s1);
    base[j + 32] = __float2half_rn(x2 * c2 + x1 * s2);
}

// ---------------------------------------------------------------------------
// NT GEMM, cp.async 3-stage pipeline, BK=64, coalesced smem-staged epilogue.
// EPI: 0 = f32 plain
//      3 = merged k|v scatter: col<3072 -> g_k, else -> g_v
//      4 = merged q|ckv scatter: col<3072 -> g_q, else -> g_ckv_pre (f16 linear)
// ---------------------------------------------------------------------------
constexpr int GBK      = 64;
constexpr int SMST     = 72;
constexpr int GSTAGES  = 3;
constexpr int STAGE_HALVES = 128 * SMST;
constexpr int GEMM_SMEM = GSTAGES * 2 * STAGE_HALVES * (int)sizeof(__half);  // 110592
constexpr int EPI_F32_STRIDE = 132;
constexpr int EPI_F16_STRIDE = 136;
static_assert(128 * EPI_F32_STRIDE * 4 <= GEMM_SMEM, "f32 stage fits");

template <int EPI>
__global__ __launch_bounds__(256, 2) void gemm_nt(const __half* __restrict__ A,
                                                  const __half* __restrict__ Bw,
                                                  float* __restrict__ outF,
                                                  __half* __restrict__ outH,
                                                  int M, int N, int K) {
    extern __shared__ __half gsm[];

    const int tid = threadIdx.x;
    const int lane = tid & 31, warp = tid >> 5;
    const int wm = (warp & 3) * 32, wn = (warp >> 2) * 64;
    const int m0 = blockIdx.y * 128, n0 = blockIdx.x * 128;

    const __half* Ag = A + (size_t)m0 * K;
    const __half* Bg = Bw + (size_t)n0 * K;

    auto stageA = [&](int s) -> __half* { return gsm + s * 2 * STAGE_HALVES; };
    auto stageB = [&](int s) -> __half* { return gsm + s * 2 * STAGE_HALVES + STAGE_HALVES; };

    auto issue = [&](int s, int kc) {
        __half* sa = stageA(s);
        __half* sb = stageB(s);
        const __half* ag = Ag + (size_t)kc * GBK;
        const __half* bg = Bg + (size_t)kc * GBK;
        #pragma unroll
        for (int p = 0; p < 4; p++) {
            int idx = tid + p * 256;
            int r = idx >> 3;
            int c = (idx & 7) * 8;
            cp16(saddr(sa + r * SMST + c), ag + (size_t)r * K + c);
            cp16(saddr(sb + r * SMST + c), bg + (size_t)r * K + c);
        }
    };

    float acc[2][8][4];
    #pragma unroll
    for (int i = 0; i < 2; i++)
        #pragma unroll
        for (int j = 0; j < 8; j++)
            #pragma unroll
            for (int r = 0; r < 4; r++) acc[i][j][r] = 0.f;

    const int nk = K / GBK;

    issue(0, 0); cp_commit();
    issue(1, 1); cp_commit();

    for (int kc = 0; kc < nk; kc++) {
        cp_wait<1>();
        __syncthreads();
        const int s = kc % 3;
        const __half* sa = stageA(s);
        const __half* sb = stageB(s);

        #pragma unroll
        for (int ks = 0; ks < 4; ks++) {
            uint32_t af[2][4];
            #pragma unroll
            for (int mi = 0; mi < 2; mi++) {
                uint32_t a = saddr(&sa[(wm + mi * 16 + (lane & 15)) * SMST + ks * 16 + (lane >> 4) * 8]);
                ldm_x4(af[mi][0], af[mi][1], af[mi][2], af[mi][3], a);
            }
            uint32_t bf[8][2];
            #pragma unroll
            for (int j = 0; j < 4; j++) {
                uint32_t r0, r1, r2, r3;
                uint32_t a = saddr(&sb[(wn + j * 16 + (lane & 15)) * SMST + ks * 16 + (lane >> 4) * 8]);
                ldm_x4(r0, r1, r2, r3, a);
                bf[2 * j + 0][0] = r0; bf[2 * j + 0][1] = r2;
                bf[2 * j + 1][0] = r1; bf[2 * j + 1][1] = r3;
            }
            #pragma unroll
            for (int mi = 0; mi < 2; mi++)
                #pragma unroll
                for (int j = 0; j < 8; j++)
                    mma_f16(acc[mi][j], af[mi], bf[j][0], bf[j][1]);
        }

        if (kc + 2 < nk) issue((kc + 2) % 3, kc + 2);
        cp_commit();
    }

    // ---------------- epilogue: stage C in smem, write coalesced ------------
    cp_wait<0>();
    __syncthreads();

    const int g = lane >> 2, t = lane & 3;
    if (EPI == 0) {
        float* cs = reinterpret_cast<float*>(gsm);
        #pragma unroll
        for (int mi = 0; mi < 2; mi++)
            #pragma unroll
            for (int j = 0; j < 8; j++)
                #pragma unroll
                for (int hh = 0; hh < 2; hh++) {
                    int r = wm + mi * 16 + g + hh * 8;
                    int c = wn + j * 8 + t * 2;
                    cs[r * EPI_F32_STRIDE + c + 0] = acc[mi][j][hh * 2 + 0];
                    cs[r * EPI_F32_STRIDE + c + 1] = acc[mi][j][hh * 2 + 1];
                }
        __syncthreads();
        #pragma unroll
        for (int p = 0; p < 16; p++) {
            int chunk = tid + p * 256;
            int r = chunk >> 5, cc = (chunk & 31) * 4;
            float4 v = *reinterpret_cast<const float4*>(&cs[r * EPI_F32_STRIDE + cc]);
            *reinterpret_cast<float4*>(&outF[(size_t)(m0 + r) * N + n0 + cc]) = v;
        }
    } else {
        __half* cs = gsm;
        #pragma unroll
        for (int mi = 0; mi < 2; mi++)
            #pragma unroll
            for (int j = 0; j < 8; j++)
                #pragma unroll
                for (int hh = 0; hh < 2; hh++) {
                    int r = wm + mi * 16 + g + hh * 8;
                    int c = wn + j * 8 + t * 2;
                    *reinterpret_cast<__half2*>(&cs[r * EPI_F16_STRIDE + c]) =
                        __floats2half2_rn(acc[mi][j][hh * 2 + 0], acc[mi][j][hh * 2 + 1]);
                }
        __syncthreads();
        #pragma unroll
        for (int p = 0; p < 8; p++) {
            int chunk = tid + p * 256;
            int r = chunk >> 4, cc = (chunk & 15) * 8;
            uint4 v = *reinterpret_cast<const uint4*>(&cs[r * EPI_F16_STRIDE + cc]);
            int row = m0 + r;
            int col = n0 + cc;
            int b = row >> 11, s = row & (Ss - 1);
            if (EPI == 3) {  // merged k|v scatter
                if (col < Hh * QHDc) {
                    int h = col / QHDc, d = col - h * QHDc;
                    size_t di = (((size_t)b * Hh + h) * Ss + s) * QHDc + d;
                    *reinterpret_cast<uint4*>(&g_k[di]) = v;
                } else {
                    int c2 = col - Hh * QHDc;
                    int h = c2 >> 7, d = c2 & (DVc - 1);
                    size_t di = (((size_t)b * Hh + h) * Ss + s) * DVc + d;
                    *reinterpret_cast<uint4*>(&g_v[di]) = v;
                }
            } else {  // EPI == 4: merged q|ckv scatter
                if (col < Hh * QHDc) {
                    int h = col / QHDc, d = col - h * QHDc;
                    size_t di = (((size_t)b * Hh + h) * Ss + s) * QHDc + d;
                    *reinterpret_cast<uint4*>(&g_q[di]) = v;
                } else {
                    size_t di = (size_t)row * Rc + (col - Hh * QHDc);
                    *reinterpret_cast<uint4*>(&g_ckv_pre[di]) = v;
                }
            }
        }
    }
}

// ---------------------------------------------------------------------------
// Flash attention: per CTA one (b,h,qtile=64 rows). 4 warps, 3 CTAs/SM.
// Cross-tile software pipeline with single K buffer:
//   K(kt+1) issued right after QK(kt) readers finish -> hidden under
//   softmax + V-wait + PV of tile kt. V(kt+1) issued after PV(kt) finishes.
// Group commit order K,V,K,V...; every consumption point uses cp_wait<1>.
// Same smem (68.6 KB -> 3 CTAs/SM) and registers as R13. No-max exp2 softmax.
// ---------------------------------------------------------------------------
constexpr int QSTRIDE = 200;  // 192 + 8 pad
constexpr int VSTRIDE = 136;  // 128 + 8 pad
constexpr int ATTN_SMEM_BYTES = (64 * QSTRIDE * 2 + 64 * VSTRIDE) * (int)sizeof(__half);

__global__ __launch_bounds__(128, 3) void attn_kernel(const __half* __restrict__ Q,
                                                      const __half* __restrict__ Kt,
                                                      const __half* __restrict__ V,
                                                      __half* __restrict__ Out) {
    extern __shared__ __half sm[];
    __half* sQ = sm;
    __half* sK = sm + 64 * QSTRIDE;
    __half* sV = sm + 2 * 64 * QSTRIDE;

    const int qt = (int)gridDim.x - 1 - (int)blockIdx.x;  // heavy tiles first
    const int h = blockIdx.y, b = blockIdx.z;
    const int tid = threadIdx.x, lane = tid & 31, warp = tid >> 5;
    const int g = lane >> 2, t = lane & 3;
    const int wq = warp * 16;

    const size_t bh = (size_t)b * Hh + h;
    const __half* Qg = Q + (bh * Ss + (size_t)qt * 64) * QHDc;
    const __half* Kg = Kt + bh * Ss * QHDc;
    const __half* Vg = V + bh * Ss * DVc;

    auto issue_k = [&](int kt) {
        #pragma unroll
        for (int p = 0; p < 12; p++) {
            int idx = tid + p * 128;
            int r = idx / 24, c = (idx % 24) * 8;
            cp16(saddr(&sK[r * QSTRIDE + c]), &Kg[((size_t)kt * 64 + r) * QHDc + c]);
        }
    };
    auto issue_v = [&](int kt) {
        #pragma unroll
        for (int p = 0; p < 8; p++) {
            int idx = tid + p * 128;
            int r = idx >> 4, c = (idx & 15) * 8;
            cp16(saddr(&sV[r * VSTRIDE + c]), &Vg[((size_t)kt * 64 + r) * DVc + c]);
        }
    };

    // prologue: Q tile (synchronous) + K(0), V(0) in flight
    #pragma unroll
    for (int p = 0; p < 12; p++) {
        int idx = tid + p * 128;
        int r = idx / 24, c = (idx % 24) * 8;
        *reinterpret_cast<uint4*>(&sQ[r * QSTRIDE + c]) =
            *reinterpret_cast<const uint4*>(&Qg[(size_t)r * QHDc + c]);
    }
    issue_k(0); cp_commit();
    issue_v(0); cp_commit();

    float o[16][4];
    #pragma unroll
    for (int i = 0; i < 16; i++)
        #pragma unroll
        for (int r = 0; r < 4; r++) o[i][r] = 0.f;
    float lrow[2] = {0.f, 0.f};
    const float scale2 = 0.07216878364870323f * 1.4426950408889634f;  // /sqrt(192)*log2e

    const int nkt = qt + 1;
    for (int kt = 0; kt < nkt; kt++) {
        // pending: {K(kt), V(kt)} -> leave V in flight, K ready
        cp_wait<1>();
        __syncthreads();

        float sacc[8][4];
        #pragma unroll
        for (int j = 0; j < 8; j++)
            #pragma unroll
            for (int r = 0; r < 4; r++) sacc[j][r] = 0.f;

        #pragma unroll
        for (int ks = 0; ks < 12; ks++) {
            uint32_t af[4];
            ldm_x4(af[0], af[1], af[2], af[3],
                   saddr(&sQ[(wq + (lane & 15)) * QSTRIDE + ks * 16 + (lane >> 4) * 8]));
            #pragma unroll
            for (int j = 0; j < 4; j++) {
                uint32_t r0, r1, r2, r3;
                ldm_x4(r0, r1, r2, r3,
                       saddr(&sK[(j * 16 + (lane & 15)) * QSTRIDE + ks * 16 + (lane >> 4) * 8]));
                mma_f16(sacc[2 * j + 0], af, r0, r2);
                mma_f16(sacc[2 * j + 1], af, r1, r3);
            }
        }

        // all sK readers done -> prefetch K(kt+1) into the same buffer,
        // hidden under softmax + V-wait + PV below.
        __syncthreads();
        if (kt + 1 < nkt) issue_k(kt + 1);
        cp_commit();  // pending: {V(kt), K(kt+1)}

        const bool diag = (kt == qt);
        #pragma unroll
        for (int hh = 0; hh < 2; hh++) {
            float sum = 0.f;
            #pragma unroll
            for (int j = 0; j < 8; j++) {
                float s0 = sacc[j][hh * 2 + 0] * scale2;
                float s1 = sacc[j][hh * 2 + 1] * scale2;
                if (diag) {
                    int col = kt * 64 + j * 8 + t * 2;
                    int qrow = qt * 64 + wq + g + hh * 8;
                    if (col > qrow)     s0 = -1e30f;
                    if (col + 1 > qrow) s1 = -1e30f;
                }
                float p0 = exp2f(s0);
                float p1 = exp2f(s1);
                sacc[j][hh * 2 + 0] = p0;
                sacc[j][hh * 2 + 1] = p1;
                sum += p0 + p1;
            }
            sum += __shfl_xor_sync(0xffffffffu, sum, 1);
            sum += __shfl_xor_sync(0xffffffffu, sum, 2);
            lrow[hh] += sum;
        }

        uint32_t pa[4][4];
        #pragma unroll
        for (int kk = 0; kk < 4; kk++) {
            pa[kk][0] = packh(sacc[2 * kk][0], sacc[2 * kk][1]);
            pa[kk][1] = packh(sacc[2 * kk][2], sacc[2 * kk][3]);
            pa[kk][2] = packh(sacc[2 * kk + 1][0], sacc[2 * kk + 1][1]);
            pa[kk][3] = packh(sacc[2 * kk + 1][2], sacc[2 * kk + 1][3]);
        }

        // V(kt) ready (K(kt+1) still in flight)
        cp_wait<1>();
        __syncthreads();

        #pragma unroll
        for (int kk = 0; kk < 4; kk++) {
            #pragma unroll
            for (int jg = 0; jg < 8; jg++) {
                uint32_t r0, r1, r2, r3;
                ldm_x4t(r0, r1, r2, r3,
                        saddr(&sV[(kk * 16 + (lane & 15)) * VSTRIDE + jg * 16 + (lane >> 4) * 8]));
                mma_f16(o[2 * jg + 0], pa[kk], r0, r1);
                mma_f16(o[2 * jg + 1], pa[kk], r2, r3);
            }
        }

        // all sV readers done -> issue V(kt+1)
        __syncthreads();
        if (kt + 1 < nkt) issue_v(kt + 1);
        cp_commit();  // pending: {K(kt+1), V(kt+1)}
    }

    float inv0 = 1.f / lrow[0];
    float inv1 = 1.f / lrow[1];
    #pragma unroll
    for (int nt = 0; nt < 16; nt++) {
        #pragma unroll
        for (int hh = 0; hh < 2; hh++) {
            float inv = hh ? inv1 : inv0;
            int srow = qt * 64 + wq + g + hh * 8;
            int col = nt * 8 + t * 2;
            __half2 hv = __floats2half2_rn(o[nt][hh * 2] * inv, o[nt][hh * 2 + 1] * inv);
            size_t di = ((size_t)b * Ss + srow) * (Hh * DVc) + (size_t)h * DVc + col;
            *reinterpret_cast<__half2*>(&Out[di]) = hv;
        }
    }
}

// ---------------------------------------------------------------------------
// Host launcher
// ---------------------------------------------------------------------------
static void* symaddr(const void* sym) {
    void* p = nullptr;
    cudaGetSymbolAddress(&p, sym);
    return p;
}

extern "C" void kernel_launch(void* const* d_in, const int* in_sizes, int n_in,
                              void* d_out, int out_size) {
    const float* hidden = (const float*)d_in[0];
    const float* Wq    = (const float*)d_in[3];
    const float* Wkvd  = (const float*)d_in[4];
    const float* normw = (const float*)d_in[5];
    const float* Wkvu  = (const float*)d_in[6];
    const float* Wkvv  = (const float*)d_in[7];
    const float* Wo    = (const float*)d_in[8];
    const float* cosT  = (const float*)d_in[9];
    const float* sinT  = (const float*)d_in[10];
    float* out = (float*)d_out;

    __half* p_hidden = (__half*)symaddr(g_hidden);
    __half* p_Wqd    = (__half*)symaddr(g_Wqd);
    __half* p_Wkvuv  = (__half*)symaddr(g_Wkvuv);
    __half* p_Wo     = (__half*)symaddr(g_Wo);
    __half* p_q      = (__half*)symaddr(g_q);
    __half* p_k      = (__half*)symaddr(g_k);
    __half* p_v      = (__half*)symaddr(g_v);
    __half* p_ckvpre = (__half*)symaddr(g_ckv_pre);
    __half* p_ckv    = (__half*)symaddr(g_ckv);
    __half* p_attn   = (__half*)symaddr(g_attn);

    // launch 0: fused convert
    cvt_all_kernel<<<(N4_TOT + 255) / 256, 256>>>(
        hidden, Wq, Wkvd, Wkvu, Wkvv, Wo,
        p_hidden, p_Wqd, p_Wkvuv, p_Wo);

    cudaFuncSetAttribute(gemm_nt<0>, cudaFuncAttributeMaxDynamicSharedMemorySize, GEMM_SMEM);
    cudaFuncSetAttribute(gemm_nt<3>, cudaFuncAttributeMaxDynamicSharedMemorySize, GEMM_SMEM);
    cudaFuncSetAttribute(gemm_nt<4>, cudaFuncAttributeMaxDynamicSharedMemorySize, GEMM_SMEM);

    // launch 1: merged q|ckv = hidden @ [Wq;Wkv_down]^T (scatter q + ckv_pre)
    gemm_nt<4><<<dim3(NQD / 128, MSc / 128), 256, GEMM_SMEM>>>(
        p_hidden, p_Wqd, nullptr, nullptr, MSc, NQD, HIDc);
    // launch 2: rmsnorm (f16 in -> f16 out)
    rmsnorm_kernel<<<MSc, 128>>>(p_ckvpre, normw, p_ckv);
    // launch 3: merged k|v = ckv @ [Wkv_up;Wkv_v]^T (PROFILED idx 3, control)
    gemm_nt<3><<<dim3(NKV / 128, MSc / 128), 256, GEMM_SMEM>>>(
        p_ckv, p_Wkvuv, nullptr, nullptr, MSc, NKV, Rc);
    // launch 4: RoPE on q and k (fused)
    {
        int total = 2 * Bb * Hh * Ss * 32;
        rope_kernel<<<(total + 255) / 256, 256>>>(p_q, p_k, cosT, sinT);
    }
    // launch 5: attention (64-row tiles, 3 CTAs/SM, cross-tile K/V pipeline)
    cudaFuncSetAttribute(attn_kernel, cudaFuncAttributeMaxDynamicSharedMemorySize,
                         ATTN_SMEM_BYTES);
    attn_kernel<<<dim3(Ss / 64, Hh, Bb), 128, ATTN_SMEM_BYTES>>>(p_q, p_k, p_v, p_attn);
    // launch 6: out = attn @ Wo^T (f32, straight to d_out)
    gemm_nt<0><<<dim3(HIDc / 128, MSc / 128), 256, GEMM_SMEM>>>(
        p_attn, p_Wo, out, nullptr, MSc, HIDc, HIDc);
}

// round 16
// speedup vs baseline: 1.0909x; 1.0112x over previous
#include <cuda_runtime.h>
#include <cuda_fp16.h>
#include <cuda_bf16.h>
#include <cstdint>
#include <cstdio>

#define DEV_INLINE __device__ __forceinline__

// ---------------------------------------------------------------------------
// Problem constants (fixed shapes)
// ---------------------------------------------------------------------------
constexpr int Bb   = 2;
constexpr int Ss   = 2048;
constexpr int HIDc = 2048;
constexpr int Hh   = 16;
constexpr int DNc  = 128;
constexpr int DRc  = 64;
constexpr int DVc  = 128;
constexpr int Rc   = 512;
constexpr int QHDc = DNc + DRc;             // 192
constexpr int MSc  = Bb * Ss;               // 4096 rows
constexpr int NKV  = Hh * QHDc + Hh * DVc;  // 5120 merged k|v cols
constexpr int NQD  = Hh * QHDc + Rc;        // 3584 merged q|ckv cols

// ---------------------------------------------------------------------------
// Scratch (static device globals; no allocation allowed)
// ---------------------------------------------------------------------------
__device__ __half g_hidden[MSc * HIDc];
__device__ __half g_Wqd [NQD * HIDc];         // rows 0..3071 = Wq, 3072..3583 = Wkv_down
__device__ __half g_Wkvuv[NKV * Rc];          // rows 0..3071 = Wkv_up, 3072..5119 = Wkv_v
__device__ __half g_Wo  [HIDc * Hh * DVc];
__device__ __half g_q   [Bb * Hh * Ss * QHDc];
__device__ __half g_k   [Bb * Hh * Ss * QHDc];
__device__ __half g_v   [Bb * Hh * Ss * DVc];
__device__ __half g_ckv_pre[MSc * Rc];        // pre-norm ckv (f16)
__device__ __half g_ckv [MSc * Rc];
__device__ __half g_attn[MSc * Hh * DVc];

// ---------------------------------------------------------------------------
// PTX helpers
// ---------------------------------------------------------------------------
DEV_INLINE uint32_t saddr(const void* p) {
    return (uint32_t)__cvta_generic_to_shared(p);
}
DEV_INLINE void ldm_x4(uint32_t& r0, uint32_t& r1, uint32_t& r2, uint32_t& r3, uint32_t a) {
    asm volatile("ldmatrix.sync.aligned.m8n8.x4.shared.b16 {%0,%1,%2,%3}, [%4];\n"
                 : "=r"(r0), "=r"(r1), "=r"(r2), "=r"(r3) : "r"(a));
}
DEV_INLINE void ldm_x4t(uint32_t& r0, uint32_t& r1, uint32_t& r2, uint32_t& r3, uint32_t a) {
    asm volatile("ldmatrix.sync.aligned.m8n8.x4.trans.shared.b16 {%0,%1,%2,%3}, [%4];\n"
                 : "=r"(r0), "=r"(r1), "=r"(r2), "=r"(r3) : "r"(a));
}
DEV_INLINE void mma_f16(float c[4], const uint32_t a[4], const uint32_t b0, const uint32_t b1) {
    asm volatile(
        "mma.sync.aligned.m16n8k16.row.col.f32.f16.f16.f32 "
        "{%0,%1,%2,%3},{%4,%5,%6,%7},{%8,%9},{%0,%1,%2,%3};\n"
        : "+f"(c[0]), "+f"(c[1]), "+f"(c[2]), "+f"(c[3])
        : "r"(a[0]), "r"(a[1]), "r"(a[2]), "r"(a[3]), "r"(b0), "r"(b1));
}
DEV_INLINE uint32_t packh(float a, float b) {
    __half2 h = __floats2half2_rn(a, b);
    return *reinterpret_cast<uint32_t*>(&h);
}

// cp.async helpers
DEV_INLINE void cp16(uint32_t dst_smem, const void* src) {
    asm volatile("cp.async.cg.shared.global [%0], [%1], 16;\n"
                 :: "r"(dst_smem), "l"(src));
}
DEV_INLINE void cp_commit() {
    asm volatile("cp.async.commit_group;\n" ::: "memory");
}
template <int N>
DEV_INLINE void cp_wait() {
    asm volatile("cp.async.wait_group %0;\n" :: "n"(N) : "memory");
}

// ---------------------------------------------------------------------------
// Fused f32 -> f16 convert for all 6 tensors (one launch).
// Wq/Wkv_down merge into g_Wqd; Wkv_up/Wkv_v merge into g_Wkvuv.
// ---------------------------------------------------------------------------
constexpr int N4_HID  = MSc * HIDc / 4;
constexpr int N4_WQ   = Hh * QHDc * HIDc / 4;
constexpr int N4_WKVD = Rc * HIDc / 4;
constexpr int N4_WKVU = Hh * QHDc * Rc / 4;
constexpr int N4_WKVV = Hh * DVc * Rc / 4;
constexpr int N4_WO   = HIDc * Hh * DVc / 4;
constexpr int N4_C0 = N4_HID;
constexpr int N4_C1 = N4_C0 + N4_WQ;
constexpr int N4_C2 = N4_C1 + N4_WKVD;
constexpr int N4_C3 = N4_C2 + N4_WKVU;
constexpr int N4_C4 = N4_C3 + N4_WKVV;
constexpr int N4_TOT = N4_C4 + N4_WO;

__global__ __launch_bounds__(256) void cvt_all_kernel(
    const float* __restrict__ hid, const float* __restrict__ wq,
    const float* __restrict__ wkvd, const float* __restrict__ wkvu,
    const float* __restrict__ wkvv, const float* __restrict__ wo,
    __half* __restrict__ d_hid, __half* __restrict__ d_wqd,
    __half* __restrict__ d_wkvuv, __half* __restrict__ d_wo) {
    int i = blockIdx.x * blockDim.x + threadIdx.x;
    if (i >= N4_TOT) return;
    const float* src;
    __half* dst;
    int j;
    if (i < N4_C0)      { src = hid;  dst = d_hid;  j = i; }
    else if (i < N4_C1) { src = wq;   dst = d_wqd;  j = i - N4_C0; }
    else if (i < N4_C2) { src = wkvd; dst = d_wqd + Hh * QHDc * HIDc; j = i - N4_C1; }
    else if (i < N4_C3) { src = wkvu; dst = d_wkvuv; j = i - N4_C2; }
    else if (i < N4_C4) { src = wkvv; dst = d_wkvuv + Hh * QHDc * Rc; j = i - N4_C3; }
    else                { src = wo;   dst = d_wo;   j = i - N4_C4; }
    float4 v = reinterpret_cast<const float4*>(src)[j];
    __half2 a = __floats2half2_rn(v.x, v.y);
    __half2 b = __floats2half2_rn(v.z, v.w);
    reinterpret_cast<__half2*>(dst)[2 * j + 0] = a;
    reinterpret_cast<__half2*>(dst)[2 * j + 1] = b;
}

// ---------------------------------------------------------------------------
// RMSNorm over R=512, f16 in -> f16 out (square-sum in f32)
// ---------------------------------------------------------------------------
__global__ __launch_bounds__(128) void rmsnorm_kernel(const __half* __restrict__ raw,
                                                      const float* __restrict__ w,
                                                      __half* __restrict__ out) {
    int row = blockIdx.x;
    const uint2* r2 = reinterpret_cast<const uint2*>(raw + (size_t)row * Rc);
    uint2 u = r2[threadIdx.x];
    __half2 h01 = *reinterpret_cast<__half2*>(&u.x);
    __half2 h23 = *reinterpret_cast<__half2*>(&u.y);
    float x0 = __low2float(h01), x1 = __high2float(h01);
    float x2 = __low2float(h23), x3 = __high2float(h23);
    float ss = x0 * x0 + x1 * x1 + x2 * x2 + x3 * x3;
    #pragma unroll
    for (int o = 16; o; o >>= 1) ss += __shfl_xor_sync(0xffffffffu, ss, o);
    __shared__ float red[4];
    if ((threadIdx.x & 31) == 0) red[threadIdx.x >> 5] = ss;
    __syncthreads();
    float tot = red[0] + red[1] + red[2] + red[3];
    float inv = rsqrtf(tot * (1.0f / (float)Rc) + 1e-5f);
    float4 wv = reinterpret_cast<const float4*>(w)[threadIdx.x];
    __half2 o0 = __floats2half2_rn(x0 * inv * wv.x, x1 * inv * wv.y);
    __half2 o1 = __floats2half2_rn(x2 * inv * wv.z, x3 * inv * wv.w);
    __half2* op = reinterpret_cast<__half2*>(out + (size_t)row * Rc + threadIdx.x * 4);
    op[0] = o0;
    op[1] = o1;
}

// ---------------------------------------------------------------------------
// RoPE in-place on q AND k, vectorized: each thread handles 2 adjacent rotary
// pairs (half2 loads/stores, float2 cos/sin). rope dims [128,192).
// ---------------------------------------------------------------------------
__global__ __launch_bounds__(256) void rope_kernel(__half* __restrict__ Xq,
                                                   __half* __restrict__ Xk,
                                                   const float* __restrict__ cosT,
                                                   const float* __restrict__ sinT) {
    int idx = blockIdx.x * blockDim.x + threadIdx.x;  // rows*16 threads
    int j2 = idx & 15;            // pair-of-pairs index 0..15
    int row = idx >> 4;
    const int nrows = Bb * Hh * Ss;
    if (row >= 2 * nrows) return;
    __half* X = (row < nrows) ? Xq : Xk;
    if (row >= nrows) row -= nrows;
    int s = row & (Ss - 1);
    __half* base = X + (size_t)row * QHDc + DNc;
    int j = j2 * 2;
    __half2 a = *reinterpret_cast<__half2*>(&base[j]);        // x1[j], x1[j+1]
    __half2 b = *reinterpret_cast<__half2*>(&base[j + 32]);   // x2[j], x2[j+1]
    float2 c1 = *reinterpret_cast<const float2*>(&cosT[s * DRc + j]);
    float2 s1 = *reinterpret_cast<const float2*>(&sinT[s * DRc + j]);
    float2 c2 = *reinterpret_cast<const float2*>(&cosT[s * DRc + 32 + j]);
    float2 s2 = *reinterpret_cast<const float2*>(&sinT[s * DRc + 32 + j]);
    float x1a = __low2float(a), x1b = __high2float(a);
    float x2a = __low2float(b), x2b = __high2float(b);
    *reinterpret_cast<__half2*>(&base[j]) =
        __floats2half2_rn(x1a * c1.x - x2a * s1.x, x1b * c1.y - x2b * s1.y);
    *reinterpret_cast<__half2*>(&base[j + 32]) =
        __floats2half2_rn(x2a * c2.x + x1a * s2.x, x2b * c2.y + x1b * s2.y);
}

// ---------------------------------------------------------------------------
// NT GEMM, cp.async 3-stage pipeline, BK=64, coalesced smem-staged epilogue.
// EPI: 0 = f32 plain
//      3 = merged k|v scatter: col<3072 -> g_k, else -> g_v
//      4 = merged q|ckv scatter: col<3072 -> g_q, else -> g_ckv_pre (f16 linear)
// ---------------------------------------------------------------------------
constexpr int GBK      = 64;
constexpr int SMST     = 72;
constexpr int GSTAGES  = 3;
constexpr int STAGE_HALVES = 128 * SMST;
constexpr int GEMM_SMEM = GSTAGES * 2 * STAGE_HALVES * (int)sizeof(__half);  // 110592
constexpr int EPI_F32_STRIDE = 132;
constexpr int EPI_F16_STRIDE = 136;
static_assert(128 * EPI_F32_STRIDE * 4 <= GEMM_SMEM, "f32 stage fits");

template <int EPI>
__global__ __launch_bounds__(256, 2) void gemm_nt(const __half* __restrict__ A,
                                                  const __half* __restrict__ Bw,
                                                  float* __restrict__ outF,
                                                  __half* __restrict__ outH,
                                                  int M, int N, int K) {
    extern __shared__ __half gsm[];

    const int tid = threadIdx.x;
    const int lane = tid & 31, warp = tid >> 5;
    const int wm = (warp & 3) * 32, wn = (warp >> 2) * 64;
    const int m0 = blockIdx.y * 128, n0 = blockIdx.x * 128;

    const __half* Ag = A + (size_t)m0 * K;
    const __half* Bg = Bw + (size_t)n0 * K;

    auto stageA = [&](int s) -> __half* { return gsm + s * 2 * STAGE_HALVES; };
    auto stageB = [&](int s) -> __half* { return gsm + s * 2 * STAGE_HALVES + STAGE_HALVES; };

    auto issue = [&](int s, int kc) {
        __half* sa = stageA(s);
        __half* sb = stageB(s);
        const __half* ag = Ag + (size_t)kc * GBK;
        const __half* bg = Bg + (size_t)kc * GBK;
        #pragma unroll
        for (int p = 0; p < 4; p++) {
            int idx = tid + p * 256;
            int r = idx >> 3;
            int c = (idx & 7) * 8;
            cp16(saddr(sa + r * SMST + c), ag + (size_t)r * K + c);
            cp16(saddr(sb + r * SMST + c), bg + (size_t)r * K + c);
        }
    };

    float acc[2][8][4];
    #pragma unroll
    for (int i = 0; i < 2; i++)
        #pragma unroll
        for (int j = 0; j < 8; j++)
            #pragma unroll
            for (int r = 0; r < 4; r++) acc[i][j][r] = 0.f;

    const int nk = K / GBK;

    issue(0, 0); cp_commit();
    issue(1, 1); cp_commit();

    for (int kc = 0; kc < nk; kc++) {
        cp_wait<1>();
        __syncthreads();
        const int s = kc % 3;
        const __half* sa = stageA(s);
        const __half* sb = stageB(s);

        #pragma unroll
        for (int ks = 0; ks < 4; ks++) {
            uint32_t af[2][4];
            #pragma unroll
            for (int mi = 0; mi < 2; mi++) {
                uint32_t a = saddr(&sa[(wm + mi * 16 + (lane & 15)) * SMST + ks * 16 + (lane >> 4) * 8]);
                ldm_x4(af[mi][0], af[mi][1], af[mi][2], af[mi][3], a);
            }
            uint32_t bf[8][2];
            #pragma unroll
            for (int j = 0; j < 4; j++) {
                uint32_t r0, r1, r2, r3;
                uint32_t a = saddr(&sb[(wn + j * 16 + (lane & 15)) * SMST + ks * 16 + (lane >> 4) * 8]);
                ldm_x4(r0, r1, r2, r3, a);
                bf[2 * j + 0][0] = r0; bf[2 * j + 0][1] = r2;
                bf[2 * j + 1][0] = r1; bf[2 * j + 1][1] = r3;
            }
            #pragma unroll
            for (int mi = 0; mi < 2; mi++)
                #pragma unroll
                for (int j = 0; j < 8; j++)
                    mma_f16(acc[mi][j], af[mi], bf[j][0], bf[j][1]);
        }

        if (kc + 2 < nk) issue((kc + 2) % 3, kc + 2);
        cp_commit();
    }

    // ---------------- epilogue: stage C in smem, write coalesced ------------
    cp_wait<0>();
    __syncthreads();

    const int g = lane >> 2, t = lane & 3;
    if (EPI == 0) {
        float* cs = reinterpret_cast<float*>(gsm);
        #pragma unroll
        for (int mi = 0; mi < 2; mi++)
            #pragma unroll
            for (int j = 0; j < 8; j++)
                #pragma unroll
                for (int hh = 0; hh < 2; hh++) {
                    int r = wm + mi * 16 + g + hh * 8;
                    int c = wn + j * 8 + t * 2;
                    cs[r * EPI_F32_STRIDE + c + 0] = acc[mi][j][hh * 2 + 0];
                    cs[r * EPI_F32_STRIDE + c + 1] = acc[mi][j][hh * 2 + 1];
                }
        __syncthreads();
        #pragma unroll
        for (int p = 0; p < 16; p++) {
            int chunk = tid + p * 256;
            int r = chunk >> 5, cc = (chunk & 31) * 4;
            float4 v = *reinterpret_cast<const float4*>(&cs[r * EPI_F32_STRIDE + cc]);
            *reinterpret_cast<float4*>(&outF[(size_t)(m0 + r) * N + n0 + cc]) = v;
        }
    } else {
        __half* cs = gsm;
        #pragma unroll
        for (int mi = 0; mi < 2; mi++)
            #pragma unroll
            for (int j = 0; j < 8; j++)
                #pragma unroll
                for (int hh = 0; hh < 2; hh++) {
                    int r = wm + mi * 16 + g + hh * 8;
                    int c = wn + j * 8 + t * 2;
                    *reinterpret_cast<__half2*>(&cs[r * EPI_F16_STRIDE + c]) =
                        __floats2half2_rn(acc[mi][j][hh * 2 + 0], acc[mi][j][hh * 2 + 1]);
                }
        __syncthreads();
        #pragma unroll
        for (int p = 0; p < 8; p++) {
            int chunk = tid + p * 256;
            int r = chunk >> 4, cc = (chunk & 15) * 8;
            uint4 v = *reinterpret_cast<const uint4*>(&cs[r * EPI_F16_STRIDE + cc]);
            int row = m0 + r;
            int col = n0 + cc;
            int b = row >> 11, s = row & (Ss - 1);
            if (EPI == 3) {  // merged k|v scatter
                if (col < Hh * QHDc) {
                    int h = col / QHDc, d = col - h * QHDc;
                    size_t di = (((size_t)b * Hh + h) * Ss + s) * QHDc + d;
                    *reinterpret_cast<uint4*>(&g_k[di]) = v;
                } else {
                    int c2 = col - Hh * QHDc;
                    int h = c2 >> 7, d = c2 & (DVc - 1);
                    size_t di = (((size_t)b * Hh + h) * Ss + s) * DVc + d;
                    *reinterpret_cast<uint4*>(&g_v[di]) = v;
                }
            } else {  // EPI == 4: merged q|ckv scatter
                if (col < Hh * QHDc) {
                    int h = col / QHDc, d = col - h * QHDc;
                    size_t di = (((size_t)b * Hh + h) * Ss + s) * QHDc + d;
                    *reinterpret_cast<uint4*>(&g_q[di]) = v;
                } else {
                    size_t di = (size_t)row * Rc + (col - Hh * QHDc);
                    *reinterpret_cast<uint4*>(&g_ckv_pre[di]) = v;
                }
            }
        }
    }
}

// ---------------------------------------------------------------------------
// Flash attention: per CTA one (b,h,qtile=64 rows). 4 warps, 3 CTAs/SM.
// Fully async pipeline: Q, K(0), V(0) issued as cp.async groups at prologue
// (commit order Q,K,V); loop-top wait<1> completes Q+K together. Cross-tile
// K/V prefetch into single buffers as in R14. No-max exp2 softmax.
// ---------------------------------------------------------------------------
constexpr int QSTRIDE = 200;  // 192 + 8 pad
constexpr int VSTRIDE = 136;  // 128 + 8 pad
constexpr int ATTN_SMEM_BYTES = (64 * QSTRIDE * 2 + 64 * VSTRIDE) * (int)sizeof(__half);

__global__ __launch_bounds__(128, 3) void attn_kernel(const __half* __restrict__ Q,
                                                      const __half* __restrict__ Kt,
                                                      const __half* __restrict__ V,
                                                      __half* __restrict__ Out) {
    extern __shared__ __half sm[];
    __half* sQ = sm;
    __half* sK = sm + 64 * QSTRIDE;
    __half* sV = sm + 2 * 64 * QSTRIDE;

    const int qt = (int)gridDim.x - 1 - (int)blockIdx.x;  // heavy tiles first
    const int h = blockIdx.y, b = blockIdx.z;
    const int tid = threadIdx.x, lane = tid & 31, warp = tid >> 5;
    const int g = lane >> 2, t = lane & 3;
    const int wq = warp * 16;

    const size_t bh = (size_t)b * Hh + h;
    const __half* Qg = Q + (bh * Ss + (size_t)qt * 64) * QHDc;
    const __half* Kg = Kt + bh * Ss * QHDc;
    const __half* Vg = V + bh * Ss * DVc;

    auto issue_k = [&](int kt) {
        #pragma unroll
        for (int p = 0; p < 12; p++) {
            int idx = tid + p * 128;
            int r = idx / 24, c = (idx % 24) * 8;
            cp16(saddr(&sK[r * QSTRIDE + c]), &Kg[((size_t)kt * 64 + r) * QHDc + c]);
        }
    };
    auto issue_v = [&](int kt) {
        #pragma unroll
        for (int p = 0; p < 8; p++) {
            int idx = tid + p * 128;
            int r = idx >> 4, c = (idx & 15) * 8;
            cp16(saddr(&sV[r * VSTRIDE + c]), &Vg[((size_t)kt * 64 + r) * DVc + c]);
        }
    };

    // prologue: Q, K(0), V(0) all as cp.async groups (commit order Q,K,V)
    #pragma unroll
    for (int p = 0; p < 12; p++) {
        int idx = tid + p * 128;
        int r = idx / 24, c = (idx % 24) * 8;
        cp16(saddr(&sQ[r * QSTRIDE + c]), &Qg[(size_t)r * QHDc + c]);
    }
    cp_commit();
    issue_k(0); cp_commit();
    issue_v(0); cp_commit();

    float o[16][4];
    #pragma unroll
    for (int i = 0; i < 16; i++)
        #pragma unroll
        for (int r = 0; r < 4; r++) o[i][r] = 0.f;
    float lrow[2] = {0.f, 0.f};
    const float scale2 = 0.07216878364870323f * 1.4426950408889634f;  // /sqrt(192)*log2e

    const int nkt = qt + 1;
    for (int kt = 0; kt < nkt; kt++) {
        // loop top pending: kt==0 -> {Q,K0,V0}; kt>0 -> {K(kt),V(kt)}.
        // wait<1> leaves only the newest (V) in flight.
        cp_wait<1>();
        __syncthreads();

        float sacc[8][4];
        #pragma unroll
        for (int j = 0; j < 8; j++)
            #pragma unroll
            for (int r = 0; r < 4; r++) sacc[j][r] = 0.f;

        #pragma unroll
        for (int ks = 0; ks < 12; ks++) {
            uint32_t af[4];
            ldm_x4(af[0], af[1], af[2], af[3],
                   saddr(&sQ[(wq + (lane & 15)) * QSTRIDE + ks * 16 + (lane >> 4) * 8]));
            #pragma unroll
            for (int j = 0; j < 4; j++) {
                uint32_t r0, r1, r2, r3;
                ldm_x4(r0, r1, r2, r3,
                       saddr(&sK[(j * 16 + (lane & 15)) * QSTRIDE + ks * 16 + (lane >> 4) * 8]));
                mma_f16(sacc[2 * j + 0], af, r0, r2);
                mma_f16(sacc[2 * j + 1], af, r1, r3);
            }
        }

        // all sK readers done -> prefetch K(kt+1) into the same buffer,
        // hidden under softmax + V-wait + PV below.
        __syncthreads();
        if (kt + 1 < nkt) issue_k(kt + 1);
        cp_commit();  // pending: {V(kt), K(kt+1)}

        const bool diag = (kt == qt);
        #pragma unroll
        for (int hh = 0; hh < 2; hh++) {
            float sum = 0.f;
            #pragma unroll
            for (int j = 0; j < 8; j++) {
                float s0 = sacc[j][hh * 2 + 0] * scale2;
                float s1 = sacc[j][hh * 2 + 1] * scale2;
                if (diag) {
                    int col = kt * 64 + j * 8 + t * 2;
                    int qrow = qt * 64 + wq + g + hh * 8;
                    if (col > qrow)     s0 = -1e30f;
                    if (col + 1 > qrow) s1 = -1e30f;
                }
                float p0 = exp2f(s0);
                float p1 = exp2f(s1);
                sacc[j][hh * 2 + 0] = p0;
                sacc[j][hh * 2 + 1] = p1;
                sum += p0 + p1;
            }
            sum += __shfl_xor_sync(0xffffffffu, sum, 1);
            sum += __shfl_xor_sync(0xffffffffu, sum, 2);
            lrow[hh] += sum;
        }

        uint32_t pa[4][4];
        #pragma unroll
        for (int kk = 0; kk < 4; kk++) {
            pa[kk][0] = packh(sacc[2 * kk][0], sacc[2 * kk][1]);
            pa[kk][1] = packh(sacc[2 * kk][2], sacc[2 * kk][3]);
            pa[kk][2] = packh(sacc[2 * kk + 1][0], sacc[2 * kk + 1][1]);
            pa[kk][3] = packh(sacc[2 * kk + 1][2], sacc[2 * kk + 1][3]);
        }

        // V(kt) ready (K(kt+1) still in flight)
        cp_wait<1>();
        __syncthreads();

        #pragma unroll
        for (int kk = 0; kk < 4; kk++) {
            #pragma unroll
            for (int jg = 0; jg < 8; jg++) {
                uint32_t r0, r1, r2, r3;
                ldm_x4t(r0, r1, r2, r3,
                        saddr(&sV[(kk * 16 + (lane & 15)) * VSTRIDE + jg * 16 + (lane >> 4) * 8]));
                mma_f16(o[2 * jg + 0], pa[kk], r0, r1);
                mma_f16(o[2 * jg + 1], pa[kk], r2, r3);
            }
        }

        // all sV readers done -> issue V(kt+1)
        __syncthreads();
        if (kt + 1 < nkt) issue_v(kt + 1);
        cp_commit();  // pending: {K(kt+1), V(kt+1)}
    }

    float inv0 = 1.f / lrow[0];
    float inv1 = 1.f / lrow[1];
    #pragma unroll
    for (int nt = 0; nt < 16; nt++) {
        #pragma unroll
        for (int hh = 0; hh < 2; hh++) {
            float inv = hh ? inv1 : inv0;
            int srow = qt * 64 + wq + g + hh * 8;
            int col = nt * 8 + t * 2;
            __half2 hv = __floats2half2_rn(o[nt][hh * 2] * inv, o[nt][hh * 2 + 1] * inv);
            size_t di = ((size_t)b * Ss + srow) * (Hh * DVc) + (size_t)h * DVc + col;
            *reinterpret_cast<__half2*>(&Out[di]) = hv;
        }
    }
}

// ---------------------------------------------------------------------------
// Host launcher
// ---------------------------------------------------------------------------
static void* symaddr(const void* sym) {
    void* p = nullptr;
    cudaGetSymbolAddress(&p, sym);
    return p;
}

extern "C" void kernel_launch(void* const* d_in, const int* in_sizes, int n_in,
                              void* d_out, int out_size) {
    const float* hidden = (const float*)d_in[0];
    const float* Wq    = (const float*)d_in[3];
    const float* Wkvd  = (const float*)d_in[4];
    const float* normw = (const float*)d_in[5];
    const float* Wkvu  = (const float*)d_in[6];
    const float* Wkvv  = (const float*)d_in[7];
    const float* Wo    = (const float*)d_in[8];
    const float* cosT  = (const float*)d_in[9];
    const float* sinT  = (const float*)d_in[10];
    float* out = (float*)d_out;

    __half* p_hidden = (__half*)symaddr(g_hidden);
    __half* p_Wqd    = (__half*)symaddr(g_Wqd);
    __half* p_Wkvuv  = (__half*)symaddr(g_Wkvuv);
    __half* p_Wo     = (__half*)symaddr(g_Wo);
    __half* p_q      = (__half*)symaddr(g_q);
    __half* p_k      = (__half*)symaddr(g_k);
    __half* p_v      = (__half*)symaddr(g_v);
    __half* p_ckvpre = (__half*)symaddr(g_ckv_pre);
    __half* p_ckv    = (__half*)symaddr(g_ckv);
    __half* p_attn   = (__half*)symaddr(g_attn);

    // launch 0: fused convert
    cvt_all_kernel<<<(N4_TOT + 255) / 256, 256>>>(
        hidden, Wq, Wkvd, Wkvu, Wkvv, Wo,
        p_hidden, p_Wqd, p_Wkvuv, p_Wo);

    cudaFuncSetAttribute(gemm_nt<0>, cudaFuncAttributeMaxDynamicSharedMemorySize, GEMM_SMEM);
    cudaFuncSetAttribute(gemm_nt<3>, cudaFuncAttributeMaxDynamicSharedMemorySize, GEMM_SMEM);
    cudaFuncSetAttribute(gemm_nt<4>, cudaFuncAttributeMaxDynamicSharedMemorySize, GEMM_SMEM);

    // launch 1: merged q|ckv = hidden @ [Wq;Wkv_down]^T (scatter q + ckv_pre)
    gemm_nt<4><<<dim3(NQD / 128, MSc / 128), 256, GEMM_SMEM>>>(
        p_hidden, p_Wqd, nullptr, nullptr, MSc, NQD, HIDc);
    // launch 2: rmsnorm (f16 in -> f16 out)
    rmsnorm_kernel<<<MSc, 128>>>(p_ckvpre, normw, p_ckv);
    // launch 3: merged k|v = ckv @ [Wkv_up;Wkv_v]^T (PROFILED idx 3, control)
    gemm_nt<3><<<dim3(NKV / 128, MSc / 128), 256, GEMM_SMEM>>>(
        p_ckv, p_Wkvuv, nullptr, nullptr, MSc, NKV, Rc);
    // launch 4: RoPE on q and k (fused, vectorized half2)
    {
        int total = 2 * Bb * Hh * Ss * 16;
        rope_kernel<<<(total + 255) / 256, 256>>>(p_q, p_k, cosT, sinT);
    }
    // launch 5: attention (64-row tiles, 3 CTAs/SM, fully async K/V/Q pipeline)
    cudaFuncSetAttribute(attn_kernel, cudaFuncAttributeMaxDynamicSharedMemorySize,
                         ATTN_SMEM_BYTES);
    attn_kernel<<<dim3(Ss / 64, Hh, Bb), 128, ATTN_SMEM_BYTES>>>(p_q, p_k, p_v, p_attn);
    // launch 6: out = attn @ Wo^T (f32, straight to d_out)
    gemm_nt<0><<<dim3(HIDc / 128, MSc / 128), 256, GEMM_SMEM>>>(
        p_attn, p_Wo, out, nullptr, MSc, HIDc, HIDc);
}